// round 3
// baseline (speedup 1.0000x reference)
#include <cuda_runtime.h>
#include <math_constants.h>
#include <cstdint>

#define Bn 4
#define Tn 1024
#define Cn 1024
#define Hn 16
#define Dn 64

// Scratch (device globals: allowed; no cudaMalloc anywhere)
__device__ float g_q[Bn * Hn * Tn * Dn];
__device__ float g_k[Bn * Hn * Tn * Dn];
__device__ float g_v[Bn * Hn * Tn * Dn];
__device__ float g_att[Bn * Tn * Hn * Dn];

// ---------------------------------------------------------------------------
// tf32 helpers
// ---------------------------------------------------------------------------
__device__ __forceinline__ uint32_t f2tf(float x) {
    uint32_t u;
    asm("cvt.rna.tf32.f32 %0, %1;" : "=r"(u) : "f"(x));
    return u;
}

__device__ __forceinline__ void mma_tf32(float c[4],
                                         uint32_t a0, uint32_t a1, uint32_t a2, uint32_t a3,
                                         uint32_t b0, uint32_t b1)
{
    asm volatile(
        "mma.sync.aligned.m16n8k8.row.col.f32.tf32.tf32.f32 "
        "{%0,%1,%2,%3}, {%4,%5,%6,%7}, {%8,%9}, {%0,%1,%2,%3};"
        : "+f"(c[0]), "+f"(c[1]), "+f"(c[2]), "+f"(c[3])
        : "r"(a0), "r"(a1), "r"(a2), "r"(a3), "r"(b0), "r"(b1));
}

// ---------------------------------------------------------------------------
// Kernel 1: fused QKV projection on tf32 tensor cores (unchanged from R2).
// ---------------------------------------------------------------------------
__global__ __launch_bounds__(256, 2) void qkv_gemm_tc(
    const float* __restrict__ x,
    const float* __restrict__ Wq,
    const float* __restrict__ Wk,
    const float* __restrict__ Wv)
{
    __shared__ uint32_t As[128 * 36];
    __shared__ uint32_t Bs[32 * 72];

    const int tid = threadIdx.x;
    const int lane = tid & 31;
    const int warp = tid >> 5;
    const int wmBase = (warp & 3) * 32;
    const int wnBase = (warp >> 2) * 32;

    const int rowBase = blockIdx.x * 128;
    const int py = blockIdx.y;
    const int proj = py >> 4;
    const int h = py & 15;

    const float* W = (proj == 0 ? Wq : (proj == 1 ? Wk : Wv)) + (size_t)h * Cn * Dn;
    float* outp = (proj == 0 ? g_q : (proj == 1 ? g_k : g_v));
    const int b  = rowBase >> 10;
    const int t0 = rowBase & (Tn - 1);
    outp += ((size_t)(b * Hn + h) * Tn + t0) * Dn;

    const float* A = x + (size_t)rowBase * Cn;

    const int aRow = tid >> 3;
    const int aCol = (tid & 7) * 4;
    const int bRow = tid >> 3;

    float4 aR[4], bR[2];
#pragma unroll
    for (int i = 0; i < 4; i++)
        aR[i] = *(const float4*)&A[(size_t)(aRow + i * 32) * Cn + aCol];
#pragma unroll
    for (int i = 0; i < 2; i++)
        bR[i] = *(const float4*)&W[(size_t)bRow * Dn + ((tid & 7) * 2 + i) * 4];

    float acc[2][4][4];
#pragma unroll
    for (int mt = 0; mt < 2; mt++)
#pragma unroll
        for (int j = 0; j < 4; j++)
#pragma unroll
            for (int e = 0; e < 4; e++) acc[mt][j][e] = 0.f;

    const int g  = lane >> 2;
    const int tg = lane & 3;

    for (int k0 = 0; k0 < Cn; k0 += 32) {
#pragma unroll
        for (int i = 0; i < 4; i++) {
            int r = aRow + i * 32;
            As[r * 36 + aCol + 0] = f2tf(aR[i].x);
            As[r * 36 + aCol + 1] = f2tf(aR[i].y);
            As[r * 36 + aCol + 2] = f2tf(aR[i].z);
            As[r * 36 + aCol + 3] = f2tf(aR[i].w);
        }
#pragma unroll
        for (int i = 0; i < 2; i++) {
            int c = ((tid & 7) * 2 + i) * 4;
            Bs[bRow * 72 + c + 0] = f2tf(bR[i].x);
            Bs[bRow * 72 + c + 1] = f2tf(bR[i].y);
            Bs[bRow * 72 + c + 2] = f2tf(bR[i].z);
            Bs[bRow * 72 + c + 3] = f2tf(bR[i].w);
        }
        __syncthreads();

        if (k0 + 32 < Cn) {
#pragma unroll
            for (int i = 0; i < 4; i++)
                aR[i] = *(const float4*)&A[(size_t)(aRow + i * 32) * Cn + k0 + 32 + aCol];
#pragma unroll
            for (int i = 0; i < 2; i++)
                bR[i] = *(const float4*)&W[(size_t)(k0 + 32 + bRow) * Dn + ((tid & 7) * 2 + i) * 4];
        }

#pragma unroll
        for (int kk = 0; kk < 4; kk++) {
            const int kb = kk * 8;
            uint32_t af[2][4], bf[4][2];
#pragma unroll
            for (int mt = 0; mt < 2; mt++) {
                int r = wmBase + mt * 16 + g;
                af[mt][0] = As[r * 36 + kb + tg];
                af[mt][1] = As[(r + 8) * 36 + kb + tg];
                af[mt][2] = As[r * 36 + kb + tg + 4];
                af[mt][3] = As[(r + 8) * 36 + kb + tg + 4];
            }
#pragma unroll
            for (int j = 0; j < 4; j++) {
                int cidx = wnBase + j * 8 + g;
                bf[j][0] = Bs[(kb + tg) * 72 + cidx];
                bf[j][1] = Bs[(kb + tg + 4) * 72 + cidx];
            }
#pragma unroll
            for (int mt = 0; mt < 2; mt++)
#pragma unroll
                for (int j = 0; j < 4; j++)
                    mma_tf32(acc[mt][j], af[mt][0], af[mt][1], af[mt][2], af[mt][3],
                             bf[j][0], bf[j][1]);
        }
        __syncthreads();
    }

#pragma unroll
    for (int mt = 0; mt < 2; mt++) {
        int row0 = wmBase + mt * 16 + g;
#pragma unroll
        for (int j = 0; j < 4; j++) {
            int col = wnBase + j * 8 + tg * 2;
            float2 lo = make_float2(acc[mt][j][0], acc[mt][j][1]);
            float2 hi = make_float2(acc[mt][j][2], acc[mt][j][3]);
            *(float2*)&outp[(size_t)row0 * Dn + col] = lo;
            *(float2*)&outp[(size_t)(row0 + 8) * Dn + col] = hi;
        }
    }
}

// ---------------------------------------------------------------------------
// Kernel 2: causal flash attention on tf32 tensor cores.
// Block = 128 queries x one (b,h). 8 warps, each owns a 16-row stripe.
// Key tiles of 64. S = Q K^T via mma (Q: A-op row-major smem stride 68;
// K: transposed Kt[d][s] stride 72 as B-op). Softmax on C fragments.
// P staged to per-warp smem stripe (tf32), O += P V via mma (V natural
// layout Vs[s][d] stride 72 as B-op since k-index = s).
// ---------------------------------------------------------------------------
#define ATTN_SMEM_U32 (128 * 68 + 128 * 68 + 64 * 72 + 64 * 72)

__global__ __launch_bounds__(256, 2) void attn_tc()
{
    extern __shared__ uint32_t smu[];
    uint32_t* Qs = smu;                   // [128][68] tf32, A-operand
    uint32_t* Ps = Qs + 128 * 68;         // [128][68] tf32, A-operand (per-warp stripes)
    uint32_t* Kt = Ps + 128 * 68;         // [64 d][72 s] tf32, B-operand
    uint32_t* Vs = Kt + 64 * 72;          // [64 s][72 d] tf32, B-operand

    const int tid = threadIdx.x;
    const int lane = tid & 31;
    const int warp = tid >> 5;
    const int g = lane >> 2;
    const int tg = lane & 3;
    const int wm = warp * 16;
    const int qt = (int)gridDim.x - 1 - (int)blockIdx.x;  // big tiles first
    const int bh = blockIdx.y;

    // ---- load Q tile (128 x 64) into Qs as tf32 ----
    {
        const float* qbase = g_q + ((size_t)bh * Tn + (size_t)qt * 128) * Dn;
        int r = tid >> 1;
        int dseg = (tid & 1) * 32;
#pragma unroll
        for (int i = 0; i < 8; i++) {
            float4 v = *(const float4*)&qbase[(size_t)r * Dn + dseg + i * 4];
            Qs[r * 68 + dseg + i * 4 + 0] = f2tf(v.x);
            Qs[r * 68 + dseg + i * 4 + 1] = f2tf(v.y);
            Qs[r * 68 + dseg + i * 4 + 2] = f2tf(v.z);
            Qs[r * 68 + dseg + i * 4 + 3] = f2tf(v.w);
        }
    }

    float m0 = -CUDART_INF_F, m1 = -CUDART_INF_F;
    float l0 = 0.f, l1 = 0.f;
    float oacc[8][4];
#pragma unroll
    for (int j = 0; j < 8; j++)
#pragma unroll
        for (int e = 0; e < 4; e++) oacc[j][e] = 0.f;

    const int row0 = qt * 128 + wm + g;
    const int row1 = row0 + 8;
    const int rowWarpMax = qt * 128 + wm + 15;

    const int nst = 2 * qt + 2;
    for (int st = 0; st < nst; st++) {
        __syncthreads();  // Kt/Vs safe to overwrite; also covers Qs on st==0

        // ---- load K (transposed) and V tiles ----
        {
            int s = tid & 63;
            int dbase = (tid >> 6) * 16;
            const float* kb_ = g_k + ((size_t)bh * Tn + (size_t)st * 64) * Dn;
            const float* vb_ = g_v + ((size_t)bh * Tn + (size_t)st * 64) * Dn;
#pragma unroll
            for (int i = 0; i < 4; i++) {
                float4 kv = *(const float4*)&kb_[(size_t)s * Dn + dbase + i * 4];
                Kt[(dbase + i * 4 + 0) * 72 + s] = f2tf(kv.x);
                Kt[(dbase + i * 4 + 1) * 72 + s] = f2tf(kv.y);
                Kt[(dbase + i * 4 + 2) * 72 + s] = f2tf(kv.z);
                Kt[(dbase + i * 4 + 3) * 72 + s] = f2tf(kv.w);
                float4 vv = *(const float4*)&vb_[(size_t)s * Dn + dbase + i * 4];
                Vs[s * 72 + dbase + i * 4 + 0] = f2tf(vv.x);
                Vs[s * 72 + dbase + i * 4 + 1] = f2tf(vv.y);
                Vs[s * 72 + dbase + i * 4 + 2] = f2tf(vv.z);
                Vs[s * 72 + dbase + i * 4 + 3] = f2tf(vv.w);
            }
        }
        __syncthreads();

        // Entire warp stripe above the diagonal? Skip compute (still did loads).
        if (st * 64 > rowWarpMax) continue;

        // ---- S = Q K^T (warp stripe: 16 x 64) ----
        float c[8][4];
#pragma unroll
        for (int j = 0; j < 8; j++)
#pragma unroll
            for (int e = 0; e < 4; e++) c[j][e] = 0.f;

#pragma unroll
        for (int kk = 0; kk < 8; kk++) {
            const int kb = kk * 8;
            uint32_t a0 = Qs[(wm + g) * 68 + kb + tg];
            uint32_t a1 = Qs[(wm + g + 8) * 68 + kb + tg];
            uint32_t a2 = Qs[(wm + g) * 68 + kb + tg + 4];
            uint32_t a3 = Qs[(wm + g + 8) * 68 + kb + tg + 4];
#pragma unroll
            for (int j = 0; j < 8; j++) {
                uint32_t b0 = Kt[(kb + tg) * 72 + j * 8 + g];
                uint32_t b1 = Kt[(kb + tg + 4) * 72 + j * 8 + g];
                mma_tf32(c[j], a0, a1, a2, a3, b0, b1);
            }
        }

        // ---- scale + causal mask ----
        const float scale = 0.125f;  // 1/sqrt(64)
        const bool maskt = (st * 64 + 63 > qt * 128);  // tile touches diagonal
#pragma unroll
        for (int j = 0; j < 8; j++) {
            int col = st * 64 + j * 8 + tg * 2;
            if (maskt) {
                c[j][0] = (col     > row0) ? -CUDART_INF_F : c[j][0] * scale;
                c[j][1] = (col + 1 > row0) ? -CUDART_INF_F : c[j][1] * scale;
                c[j][2] = (col     > row1) ? -CUDART_INF_F : c[j][2] * scale;
                c[j][3] = (col + 1 > row1) ? -CUDART_INF_F : c[j][3] * scale;
            } else {
                c[j][0] *= scale; c[j][1] *= scale;
                c[j][2] *= scale; c[j][3] *= scale;
            }
        }

        // ---- online softmax on fragments ----
        float t0 = -CUDART_INF_F, t1 = -CUDART_INF_F;
#pragma unroll
        for (int j = 0; j < 8; j++) {
            t0 = fmaxf(t0, fmaxf(c[j][0], c[j][1]));
            t1 = fmaxf(t1, fmaxf(c[j][2], c[j][3]));
        }
        t0 = fmaxf(t0, __shfl_xor_sync(0xffffffffu, t0, 1));
        t0 = fmaxf(t0, __shfl_xor_sync(0xffffffffu, t0, 2));
        t1 = fmaxf(t1, __shfl_xor_sync(0xffffffffu, t1, 1));
        t1 = fmaxf(t1, __shfl_xor_sync(0xffffffffu, t1, 2));

        float nm0 = fmaxf(m0, t0), nm1 = fmaxf(m1, t1);
        float al0 = __expf(m0 - nm0), al1 = __expf(m1 - nm1);
        float s0 = 0.f, s1 = 0.f;
#pragma unroll
        for (int j = 0; j < 8; j++) {
            float p0 = __expf(c[j][0] - nm0);
            float p1 = __expf(c[j][1] - nm0);
            float p2 = __expf(c[j][2] - nm1);
            float p3 = __expf(c[j][3] - nm1);
            s0 += p0 + p1;
            s1 += p2 + p3;
            int col = j * 8 + tg * 2;
            Ps[(wm + g) * 68 + col]     = f2tf(p0);
            Ps[(wm + g) * 68 + col + 1] = f2tf(p1);
            Ps[(wm + g + 8) * 68 + col]     = f2tf(p2);
            Ps[(wm + g + 8) * 68 + col + 1] = f2tf(p3);
        }
        s0 += __shfl_xor_sync(0xffffffffu, s0, 1);
        s0 += __shfl_xor_sync(0xffffffffu, s0, 2);
        s1 += __shfl_xor_sync(0xffffffffu, s1, 1);
        s1 += __shfl_xor_sync(0xffffffffu, s1, 2);

        l0 = l0 * al0 + s0;  m0 = nm0;
        l1 = l1 * al1 + s1;  m1 = nm1;

#pragma unroll
        for (int j = 0; j < 8; j++) {
            oacc[j][0] *= al0; oacc[j][1] *= al0;
            oacc[j][2] *= al1; oacc[j][3] *= al1;
        }
        __syncwarp();

        // ---- O += P V (warp stripe 16 x 64, k = 64 keys) ----
#pragma unroll
        for (int kk = 0; kk < 8; kk++) {
            const int kb = kk * 8;
            uint32_t a0 = Ps[(wm + g) * 68 + kb + tg];
            uint32_t a1 = Ps[(wm + g + 8) * 68 + kb + tg];
            uint32_t a2 = Ps[(wm + g) * 68 + kb + tg + 4];
            uint32_t a3 = Ps[(wm + g + 8) * 68 + kb + tg + 4];
#pragma unroll
            for (int j = 0; j < 8; j++) {
                uint32_t b0 = Vs[(kb + tg) * 72 + j * 8 + g];
                uint32_t b1 = Vs[(kb + tg + 4) * 72 + j * 8 + g];
                mma_tf32(oacc[j], a0, a1, a2, a3, b0, b1);
            }
        }
    }

    // ---- epilogue: normalize and write to g_att [b][t][h*D + d] ----
    const int b = bh >> 4, h = bh & 15;
    float* ob = g_att + ((size_t)b * Tn + (size_t)qt * 128) * (Hn * Dn) + h * Dn;
    float inv0 = 1.f / l0, inv1 = 1.f / l1;
#pragma unroll
    for (int j = 0; j < 8; j++) {
        int col = j * 8 + tg * 2;
        *(float2*)&ob[(size_t)(wm + g) * (Hn * Dn) + col] =
            make_float2(oacc[j][0] * inv0, oacc[j][1] * inv0);
        *(float2*)&ob[(size_t)(wm + g + 8) * (Hn * Dn) + col] =
            make_float2(oacc[j][2] * inv1, oacc[j][3] * inv1);
    }
}

// ---------------------------------------------------------------------------
// Kernel 3: output projection on tf32 tensor cores (unchanged from R2).
// ---------------------------------------------------------------------------
__global__ __launch_bounds__(256, 2) void proj_gemm_tc(
    const float* __restrict__ Wp,
    const float* __restrict__ bp,
    float* __restrict__ out)
{
    __shared__ uint32_t As[128 * 36];
    __shared__ uint32_t Bs[32 * 72];

    const int tid = threadIdx.x;
    const int lane = tid & 31;
    const int warp = tid >> 5;
    const int wmBase = (warp & 3) * 32;
    const int wnBase = (warp >> 2) * 32;

    const int rowBase = blockIdx.x * 128;
    const int n0 = blockIdx.y * 64;

    const float* A = g_att + (size_t)rowBase * Cn;
    float* O = out + (size_t)rowBase * Cn + n0;

    const int aRow = tid >> 3;
    const int aCol = (tid & 7) * 4;
    const int bRow = tid >> 3;

    float4 aR[4], bR[2];
#pragma unroll
    for (int i = 0; i < 4; i++)
        aR[i] = *(const float4*)&A[(size_t)(aRow + i * 32) * Cn + aCol];
#pragma unroll
    for (int i = 0; i < 2; i++)
        bR[i] = *(const float4*)&Wp[(size_t)bRow * Cn + n0 + ((tid & 7) * 2 + i) * 4];

    float acc[2][4][4];
#pragma unroll
    for (int mt = 0; mt < 2; mt++)
#pragma unroll
        for (int j = 0; j < 4; j++)
#pragma unroll
            for (int e = 0; e < 4; e++) acc[mt][j][e] = 0.f;

    const int g  = lane >> 2;
    const int tg = lane & 3;

    for (int k0 = 0; k0 < Cn; k0 += 32) {
#pragma unroll
        for (int i = 0; i < 4; i++) {
            int r = aRow + i * 32;
            As[r * 36 + aCol + 0] = f2tf(aR[i].x);
            As[r * 36 + aCol + 1] = f2tf(aR[i].y);
            As[r * 36 + aCol + 2] = f2tf(aR[i].z);
            As[r * 36 + aCol + 3] = f2tf(aR[i].w);
        }
#pragma unroll
        for (int i = 0; i < 2; i++) {
            int c = ((tid & 7) * 2 + i) * 4;
            Bs[bRow * 72 + c + 0] = f2tf(bR[i].x);
            Bs[bRow * 72 + c + 1] = f2tf(bR[i].y);
            Bs[bRow * 72 + c + 2] = f2tf(bR[i].z);
            Bs[bRow * 72 + c + 3] = f2tf(bR[i].w);
        }
        __syncthreads();

        if (k0 + 32 < Cn) {
#pragma unroll
            for (int i = 0; i < 4; i++)
                aR[i] = *(const float4*)&A[(size_t)(aRow + i * 32) * Cn + k0 + 32 + aCol];
#pragma unroll
            for (int i = 0; i < 2; i++)
                bR[i] = *(const float4*)&Wp[(size_t)(k0 + 32 + bRow) * Cn + n0 + ((tid & 7) * 2 + i) * 4];
        }

#pragma unroll
        for (int kk = 0; kk < 4; kk++) {
            const int kb = kk * 8;
            uint32_t af[2][4], bf[4][2];
#pragma unroll
            for (int mt = 0; mt < 2; mt++) {
                int r = wmBase + mt * 16 + g;
                af[mt][0] = As[r * 36 + kb + tg];
                af[mt][1] = As[(r + 8) * 36 + kb + tg];
                af[mt][2] = As[r * 36 + kb + tg + 4];
                af[mt][3] = As[(r + 8) * 36 + kb + tg + 4];
            }
#pragma unroll
            for (int j = 0; j < 4; j++) {
                int cidx = wnBase + j * 8 + g;
                bf[j][0] = Bs[(kb + tg) * 72 + cidx];
                bf[j][1] = Bs[(kb + tg + 4) * 72 + cidx];
            }
#pragma unroll
            for (int mt = 0; mt < 2; mt++)
#pragma unroll
                for (int j = 0; j < 4; j++)
                    mma_tf32(acc[mt][j], af[mt][0], af[mt][1], af[mt][2], af[mt][3],
                             bf[j][0], bf[j][1]);
        }
        __syncthreads();
    }

#pragma unroll
    for (int mt = 0; mt < 2; mt++) {
        int row0 = wmBase + mt * 16 + g;
#pragma unroll
        for (int j = 0; j < 4; j++) {
            int col = wnBase + j * 8 + tg * 2;
            float b0 = bp[n0 + col];
            float b1 = bp[n0 + col + 1];
            float2 lo = make_float2(acc[mt][j][0] + b0, acc[mt][j][1] + b1);
            float2 hi = make_float2(acc[mt][j][2] + b0, acc[mt][j][3] + b1);
            *(float2*)&O[(size_t)row0 * Cn + col] = lo;
            *(float2*)&O[(size_t)(row0 + 8) * Cn + col] = hi;
        }
    }
}

// ---------------------------------------------------------------------------

extern "C" void kernel_launch(void* const* d_in, const int* in_sizes, int n_in,
                              void* d_out, int out_size)
{
    (void)in_sizes; (void)n_in; (void)out_size;
    const float* x  = (const float*)d_in[0];
    const float* Wq = (const float*)d_in[1];
    const float* Wk = (const float*)d_in[2];
    const float* Wv = (const float*)d_in[3];
    const float* Wp = (const float*)d_in[4];
    const float* bp = (const float*)d_in[5];
    float* out = (float*)d_out;

    const size_t attn_smem = ATTN_SMEM_U32 * sizeof(uint32_t);  // ~104 KB
    cudaFuncSetAttribute(attn_tc,
                         cudaFuncAttributeMaxDynamicSharedMemorySize,
                         (int)attn_smem);

    qkv_gemm_tc<<<dim3(32, 48), 256>>>(x, Wq, Wk, Wv);
    attn_tc<<<dim3(Tn / 128, Bn * Hn), 256, attn_smem>>>();
    proj_gemm_tc<<<dim3(32, 16), 256>>>(Wp, bp, out);
}

// round 4
// speedup vs baseline: 1.6218x; 1.6218x over previous
#include <cuda_runtime.h>
#include <cuda_fp16.h>
#include <math_constants.h>
#include <cstdint>

#define Bn 4
#define Tn 1024
#define Cn 1024
#define Hn 16
#define Dn 64

// fp16 scratch (device globals; no cudaMalloc anywhere)
__device__ __half g_hx[Bn * Tn * Cn];                  // x in fp16 [4096][1024]
__device__ __half g_hw[3 * Hn * Dn * Cn];              // W^T fp16 [proj*16+h][n=64][k=1024]
__device__ __half g_hwpt[Cn * Cn];                     // Wp^T fp16 [n=1024][k=1024]
__device__ __half g_qh[Bn * Hn * Tn * Dn];
__device__ __half g_kh[Bn * Hn * Tn * Dn];
__device__ __half g_vh[Bn * Hn * Tn * Dn];
__device__ __half g_atth[Bn * Tn * Hn * Dn];           // [b][t][h*64+d] fp16

// ---------------------------------------------------------------------------
// fp16 mma m16n8k16 (row.col, fp32 accumulate)
// ---------------------------------------------------------------------------
__device__ __forceinline__ void mma_f16(float c[4],
                                        uint32_t a0, uint32_t a1, uint32_t a2, uint32_t a3,
                                        uint32_t b0, uint32_t b1)
{
    asm volatile(
        "mma.sync.aligned.m16n8k16.row.col.f32.f16.f16.f32 "
        "{%0,%1,%2,%3}, {%4,%5,%6,%7}, {%8,%9}, {%0,%1,%2,%3};"
        : "+f"(c[0]), "+f"(c[1]), "+f"(c[2]), "+f"(c[3])
        : "r"(a0), "r"(a1), "r"(a2), "r"(a3), "r"(b0), "r"(b1));
}

__device__ __forceinline__ uint32_t ldsm_u32(const __half* p) {
    return *(const uint32_t*)p;
}

// ---------------------------------------------------------------------------
// Convert x -> fp16 (elementwise)
// ---------------------------------------------------------------------------
__global__ __launch_bounds__(256) void conv_x_kernel(const float* __restrict__ src)
{
    int i = (blockIdx.x * 256 + threadIdx.x) * 4;
    float4 v = *(const float4*)&src[i];
    __half2 h0 = __floats2half2_rn(v.x, v.y);
    __half2 h1 = __floats2half2_rn(v.z, v.w);
    uint2 pk = make_uint2(*(uint32_t*)&h0, *(uint32_t*)&h1);
    *(uint2*)&g_hx[i] = pk;
}

// ---------------------------------------------------------------------------
// Transpose + convert: src fp32 [nmat][R][C] -> dst fp16 [nmat][C][R]
// 32x32 smem tiles, 256 threads.
// ---------------------------------------------------------------------------
__global__ __launch_bounds__(256) void transcvt_kernel(
    const float* __restrict__ src, __half* __restrict__ dst, int R, int C)
{
    __shared__ float tile[32][33];
    const int tid = threadIdx.x;
    const int m = blockIdx.z;
    src += (size_t)m * R * C;
    dst += (size_t)m * R * C;
    const int r0 = blockIdx.y * 32;
    const int c0 = blockIdx.x * 32;

    {
        int rr = tid >> 3;
        int cc = (tid & 7) * 4;
        float4 v = *(const float4*)&src[(size_t)(r0 + rr) * C + c0 + cc];
        tile[rr][cc + 0] = v.x;
        tile[rr][cc + 1] = v.y;
        tile[rr][cc + 2] = v.z;
        tile[rr][cc + 3] = v.w;
    }
    __syncthreads();
    {
        int cw = tid >> 3;
        int rw = (tid & 7) * 4;
        __half2 h0 = __floats2half2_rn(tile[rw + 0][cw], tile[rw + 1][cw]);
        __half2 h1 = __floats2half2_rn(tile[rw + 2][cw], tile[rw + 3][cw]);
        uint2 pk = make_uint2(*(uint32_t*)&h0, *(uint32_t*)&h1);
        *(uint2*)&dst[(size_t)(c0 + cw) * R + r0 + rw] = pk;
    }
}

// ---------------------------------------------------------------------------
// Kernel 1: fused QKV projection, fp16 mma.
// A = g_hx [4096][1024]; B = g_hw[py] [n=64][k=1024]. Block tile 128x64,
// K-chunk 64. 8 warps = 4m x 2n, warp tile 32x32, mma m16n8k16.
// ---------------------------------------------------------------------------
__global__ __launch_bounds__(256, 2) void qkv_fp16()
{
    __shared__ __align__(16) __half As[128 * 72];
    __shared__ __align__(16) __half Bs[64 * 72];

    const int tid = threadIdx.x;
    const int lane = tid & 31;
    const int warp = tid >> 5;
    const int g = lane >> 2;
    const int tg = lane & 3;
    const int wmBase = (warp & 3) * 32;
    const int wnBase = (warp >> 2) * 32;

    const int rowBase = blockIdx.x * 128;
    const int py = blockIdx.y;            // proj*16 + h
    const int proj = py >> 4;
    const int h = py & 15;

    const __half* A = g_hx + (size_t)rowBase * Cn;
    const __half* B = g_hw + (size_t)py * Dn * Cn;

    __half* outp = (proj == 0 ? g_qh : (proj == 1 ? g_kh : g_vh));
    const int b  = rowBase >> 10;
    const int t0 = rowBase & (Tn - 1);
    outp += ((size_t)(b * Hn + h) * Tn + t0) * Dn;

    const int ar = tid >> 1;              // 0..127
    const int ah = (tid & 1) * 32;        // half offset within 64
    const int bn = tid >> 2;              // 0..63
    const int bh_ = (tid & 3) * 16;       // half offset

    uint4 aR[4], bR[2];
#pragma unroll
    for (int i = 0; i < 4; i++)
        aR[i] = *(const uint4*)&A[(size_t)ar * Cn + ah + i * 8];
#pragma unroll
    for (int i = 0; i < 2; i++)
        bR[i] = *(const uint4*)&B[(size_t)bn * Cn + bh_ + i * 8];

    float acc[2][4][4];
#pragma unroll
    for (int mt = 0; mt < 2; mt++)
#pragma unroll
        for (int j = 0; j < 4; j++)
#pragma unroll
            for (int e = 0; e < 4; e++) acc[mt][j][e] = 0.f;

    for (int k0 = 0; k0 < Cn; k0 += 64) {
#pragma unroll
        for (int i = 0; i < 4; i++)
            *(uint4*)&As[ar * 72 + ah + i * 8] = aR[i];
#pragma unroll
        for (int i = 0; i < 2; i++)
            *(uint4*)&Bs[bn * 72 + bh_ + i * 8] = bR[i];
        __syncthreads();

        if (k0 + 64 < Cn) {
#pragma unroll
            for (int i = 0; i < 4; i++)
                aR[i] = *(const uint4*)&A[(size_t)ar * Cn + k0 + 64 + ah + i * 8];
#pragma unroll
            for (int i = 0; i < 2; i++)
                bR[i] = *(const uint4*)&B[(size_t)bn * Cn + k0 + 64 + bh_ + i * 8];
        }

#pragma unroll
        for (int kk = 0; kk < 4; kk++) {
            const int kb = kk * 16;
            uint32_t af[2][4], bf[4][2];
#pragma unroll
            for (int mt = 0; mt < 2; mt++) {
                int r = wmBase + mt * 16 + g;
                af[mt][0] = ldsm_u32(&As[r * 72 + kb + 2 * tg]);
                af[mt][1] = ldsm_u32(&As[(r + 8) * 72 + kb + 2 * tg]);
                af[mt][2] = ldsm_u32(&As[r * 72 + kb + 2 * tg + 8]);
                af[mt][3] = ldsm_u32(&As[(r + 8) * 72 + kb + 2 * tg + 8]);
            }
#pragma unroll
            for (int j = 0; j < 4; j++) {
                int n = wnBase + j * 8 + g;
                bf[j][0] = ldsm_u32(&Bs[n * 72 + kb + 2 * tg]);
                bf[j][1] = ldsm_u32(&Bs[n * 72 + kb + 2 * tg + 8]);
            }
#pragma unroll
            for (int mt = 0; mt < 2; mt++)
#pragma unroll
                for (int j = 0; j < 4; j++)
                    mma_f16(acc[mt][j], af[mt][0], af[mt][1], af[mt][2], af[mt][3],
                            bf[j][0], bf[j][1]);
        }
        __syncthreads();
    }

#pragma unroll
    for (int mt = 0; mt < 2; mt++) {
        int row0 = wmBase + mt * 16 + g;
#pragma unroll
        for (int j = 0; j < 4; j++) {
            int col = wnBase + j * 8 + tg * 2;
            __half2 lo = __floats2half2_rn(acc[mt][j][0], acc[mt][j][1]);
            __half2 hi = __floats2half2_rn(acc[mt][j][2], acc[mt][j][3]);
            *(__half2*)&outp[(size_t)row0 * Dn + col] = lo;
            *(__half2*)&outp[(size_t)(row0 + 8) * Dn + col] = hi;
        }
    }
}

// ---------------------------------------------------------------------------
// Kernel 2: causal flash attention, fp16 mma.
// Block = 128 queries x one (b,h). 8 warps x 16-row stripes. Key tiles 64.
// K natural [s][d] = B operand layout; V transposed in smem to Vt[d][s].
// ---------------------------------------------------------------------------
#define ATTN_SMEM_HALFS (128 * 72 + 128 * 72 + 64 * 72 + 64 * 72)

__global__ __launch_bounds__(256) void attn_fp16()
{
    extern __shared__ __align__(16) __half smh[];
    __half* Qs = smh;                    // [128][72]
    __half* Ps = Qs + 128 * 72;          // [128][72]
    __half* Ks = Ps + 128 * 72;          // [64 s][72 d]  (B for S)
    __half* Vt = Ks + 64 * 72;           // [64 d][72 s]  (B for PV)

    const int tid = threadIdx.x;
    const int lane = tid & 31;
    const int warp = tid >> 5;
    const int g = lane >> 2;
    const int tg = lane & 3;
    const int wm = warp * 16;
    const int qt = (int)gridDim.x - 1 - (int)blockIdx.x;
    const int bh = blockIdx.y;

    // ---- load Q tile (128 x 64 halfs) ----
    {
        const __half* qb = g_qh + ((size_t)bh * Tn + (size_t)qt * 128) * Dn;
        int r = tid >> 1;
        int hs = (tid & 1) * 32;
#pragma unroll
        for (int i = 0; i < 4; i++)
            *(uint4*)&Qs[r * 72 + hs + i * 8] =
                *(const uint4*)&qb[(size_t)r * Dn + hs + i * 8];
    }

    float m0 = -CUDART_INF_F, m1 = -CUDART_INF_F;
    float l0 = 0.f, l1 = 0.f;
    float oacc[8][4];
#pragma unroll
    for (int j = 0; j < 8; j++)
#pragma unroll
        for (int e = 0; e < 4; e++) oacc[j][e] = 0.f;

    const int row0 = qt * 128 + wm + g;
    const int row1 = row0 + 8;
    const int rowWarpMax = qt * 128 + wm + 15;

    const int nst = 2 * qt + 2;
    for (int st = 0; st < nst; st++) {
        __syncthreads();

        // ---- load K natural; V transposed ----
        {
            const __half* kb_ = g_kh + ((size_t)bh * Tn + (size_t)st * 64) * Dn;
            int s = tid >> 2;
            int hs = (tid & 3) * 16;
#pragma unroll
            for (int i = 0; i < 2; i++)
                *(uint4*)&Ks[s * 72 + hs + i * 8] =
                    *(const uint4*)&kb_[(size_t)s * Dn + hs + i * 8];

            const __half* vb_ = g_vh + ((size_t)bh * Tn + (size_t)st * 64) * Dn;
            int s2 = 2 * lane;
            int dbase = warp * 8;
            uint4 v0 = *(const uint4*)&vb_[(size_t)s2 * Dn + dbase];
            uint4 v1 = *(const uint4*)&vb_[(size_t)(s2 + 1) * Dn + dbase];
            const __half* p0 = (const __half*)&v0;
            const __half* p1 = (const __half*)&v1;
#pragma unroll
            for (int i = 0; i < 8; i++) {
                __half2 pk = __halves2half2(p0[i], p1[i]);
                *(__half2*)&Vt[(dbase + i) * 72 + s2] = pk;
            }
        }
        __syncthreads();

        if (st * 64 > rowWarpMax) continue;

        // ---- S = Q K^T (16 x 64 per warp) ----
        float c[8][4];
#pragma unroll
        for (int j = 0; j < 8; j++)
#pragma unroll
            for (int e = 0; e < 4; e++) c[j][e] = 0.f;

#pragma unroll
        for (int kk = 0; kk < 4; kk++) {
            const int kb = kk * 16;
            uint32_t a0 = ldsm_u32(&Qs[(wm + g) * 72 + kb + 2 * tg]);
            uint32_t a1 = ldsm_u32(&Qs[(wm + g + 8) * 72 + kb + 2 * tg]);
            uint32_t a2 = ldsm_u32(&Qs[(wm + g) * 72 + kb + 2 * tg + 8]);
            uint32_t a3 = ldsm_u32(&Qs[(wm + g + 8) * 72 + kb + 2 * tg + 8]);
#pragma unroll
            for (int j = 0; j < 8; j++) {
                int s = j * 8 + g;
                uint32_t b0 = ldsm_u32(&Ks[s * 72 + kb + 2 * tg]);
                uint32_t b1 = ldsm_u32(&Ks[s * 72 + kb + 2 * tg + 8]);
                mma_f16(c[j], a0, a1, a2, a3, b0, b1);
            }
        }

        // ---- scale + causal mask ----
        const float scale = 0.125f;
        const bool maskt = (st * 64 + 63 > qt * 128);
#pragma unroll
        for (int j = 0; j < 8; j++) {
            int col = st * 64 + j * 8 + tg * 2;
            if (maskt) {
                c[j][0] = (col     > row0) ? -CUDART_INF_F : c[j][0] * scale;
                c[j][1] = (col + 1 > row0) ? -CUDART_INF_F : c[j][1] * scale;
                c[j][2] = (col     > row1) ? -CUDART_INF_F : c[j][2] * scale;
                c[j][3] = (col + 1 > row1) ? -CUDART_INF_F : c[j][3] * scale;
            } else {
                c[j][0] *= scale; c[j][1] *= scale;
                c[j][2] *= scale; c[j][3] *= scale;
            }
        }

        // ---- online softmax ----
        float t0 = -CUDART_INF_F, t1 = -CUDART_INF_F;
#pragma unroll
        for (int j = 0; j < 8; j++) {
            t0 = fmaxf(t0, fmaxf(c[j][0], c[j][1]));
            t1 = fmaxf(t1, fmaxf(c[j][2], c[j][3]));
        }
        t0 = fmaxf(t0, __shfl_xor_sync(0xffffffffu, t0, 1));
        t0 = fmaxf(t0, __shfl_xor_sync(0xffffffffu, t0, 2));
        t1 = fmaxf(t1, __shfl_xor_sync(0xffffffffu, t1, 1));
        t1 = fmaxf(t1, __shfl_xor_sync(0xffffffffu, t1, 2));

        float nm0 = fmaxf(m0, t0), nm1 = fmaxf(m1, t1);
        float al0 = __expf(m0 - nm0), al1 = __expf(m1 - nm1);
        float s0 = 0.f, s1 = 0.f;
#pragma unroll
        for (int j = 0; j < 8; j++) {
            float p0 = __expf(c[j][0] - nm0);
            float p1 = __expf(c[j][1] - nm0);
            float p2 = __expf(c[j][2] - nm1);
            float p3 = __expf(c[j][3] - nm1);
            s0 += p0 + p1;
            s1 += p2 + p3;
            int col = j * 8 + tg * 2;
            *(__half2*)&Ps[(wm + g) * 72 + col] = __floats2half2_rn(p0, p1);
            *(__half2*)&Ps[(wm + g + 8) * 72 + col] = __floats2half2_rn(p2, p3);
        }
        s0 += __shfl_xor_sync(0xffffffffu, s0, 1);
        s0 += __shfl_xor_sync(0xffffffffu, s0, 2);
        s1 += __shfl_xor_sync(0xffffffffu, s1, 1);
        s1 += __shfl_xor_sync(0xffffffffu, s1, 2);

        l0 = l0 * al0 + s0;  m0 = nm0;
        l1 = l1 * al1 + s1;  m1 = nm1;

#pragma unroll
        for (int j = 0; j < 8; j++) {
            oacc[j][0] *= al0; oacc[j][1] *= al0;
            oacc[j][2] *= al1; oacc[j][3] *= al1;
        }
        __syncwarp();

        // ---- O += P V ----
#pragma unroll
        for (int kk = 0; kk < 4; kk++) {
            const int kb = kk * 16;
            uint32_t a0 = ldsm_u32(&Ps[(wm + g) * 72 + kb + 2 * tg]);
            uint32_t a1 = ldsm_u32(&Ps[(wm + g + 8) * 72 + kb + 2 * tg]);
            uint32_t a2 = ldsm_u32(&Ps[(wm + g) * 72 + kb + 2 * tg + 8]);
            uint32_t a3 = ldsm_u32(&Ps[(wm + g + 8) * 72 + kb + 2 * tg + 8]);
#pragma unroll
            for (int j = 0; j < 8; j++) {
                int d = j * 8 + g;
                uint32_t b0 = ldsm_u32(&Vt[d * 72 + kb + 2 * tg]);
                uint32_t b1 = ldsm_u32(&Vt[d * 72 + kb + 2 * tg + 8]);
                mma_f16(oacc[j], a0, a1, a2, a3, b0, b1);
            }
        }
    }

    // ---- epilogue -> g_atth [b][t][h*64+d] fp16 ----
    const int b = bh >> 4, h = bh & 15;
    __half* ob = g_atth + ((size_t)b * Tn + (size_t)qt * 128) * (Hn * Dn) + h * Dn;
    float inv0 = 1.f / l0, inv1 = 1.f / l1;
#pragma unroll
    for (int j = 0; j < 8; j++) {
        int col = j * 8 + tg * 2;
        *(__half2*)&ob[(size_t)(wm + g) * (Hn * Dn) + col] =
            __floats2half2_rn(oacc[j][0] * inv0, oacc[j][1] * inv0);
        *(__half2*)&ob[(size_t)(wm + g + 8) * (Hn * Dn) + col] =
            __floats2half2_rn(oacc[j][2] * inv1, oacc[j][3] * inv1);
    }
}

// ---------------------------------------------------------------------------
// Kernel 3: output projection, fp16 mma. A = g_atth [4096][1024],
// B = g_hwpt [n=1024][k=1024]. Block tile 128x64, K-chunk 64.
// ---------------------------------------------------------------------------
__global__ __launch_bounds__(256, 2) void proj_fp16(
    const float* __restrict__ bp, float* __restrict__ out)
{
    __shared__ __align__(16) __half As[128 * 72];
    __shared__ __align__(16) __half Bs[64 * 72];

    const int tid = threadIdx.x;
    const int lane = tid & 31;
    const int warp = tid >> 5;
    const int g = lane >> 2;
    const int tg = lane & 3;
    const int wmBase = (warp & 3) * 32;
    const int wnBase = (warp >> 2) * 32;

    const int rowBase = blockIdx.x * 128;
    const int n0 = blockIdx.y * 64;

    const __half* A = g_atth + (size_t)rowBase * Cn;
    const __half* B = g_hwpt + (size_t)n0 * Cn;
    float* O = out + (size_t)rowBase * Cn + n0;

    const int ar = tid >> 1;
    const int ah = (tid & 1) * 32;
    const int bn = tid >> 2;
    const int bh_ = (tid & 3) * 16;

    uint4 aR[4], bR[2];
#pragma unroll
    for (int i = 0; i < 4; i++)
        aR[i] = *(const uint4*)&A[(size_t)ar * Cn + ah + i * 8];
#pragma unroll
    for (int i = 0; i < 2; i++)
        bR[i] = *(const uint4*)&B[(size_t)bn * Cn + bh_ + i * 8];

    float acc[2][4][4];
#pragma unroll
    for (int mt = 0; mt < 2; mt++)
#pragma unroll
        for (int j = 0; j < 4; j++)
#pragma unroll
            for (int e = 0; e < 4; e++) acc[mt][j][e] = 0.f;

    for (int k0 = 0; k0 < Cn; k0 += 64) {
#pragma unroll
        for (int i = 0; i < 4; i++)
            *(uint4*)&As[ar * 72 + ah + i * 8] = aR[i];
#pragma unroll
        for (int i = 0; i < 2; i++)
            *(uint4*)&Bs[bn * 72 + bh_ + i * 8] = bR[i];
        __syncthreads();

        if (k0 + 64 < Cn) {
#pragma unroll
            for (int i = 0; i < 4; i++)
                aR[i] = *(const uint4*)&A[(size_t)ar * Cn + k0 + 64 + ah + i * 8];
#pragma unroll
            for (int i = 0; i < 2; i++)
                bR[i] = *(const uint4*)&B[(size_t)bn * Cn + k0 + 64 + bh_ + i * 8];
        }

#pragma unroll
        for (int kk = 0; kk < 4; kk++) {
            const int kb = kk * 16;
            uint32_t af[2][4], bf[4][2];
#pragma unroll
            for (int mt = 0; mt < 2; mt++) {
                int r = wmBase + mt * 16 + g;
                af[mt][0] = ldsm_u32(&As[r * 72 + kb + 2 * tg]);
                af[mt][1] = ldsm_u32(&As[(r + 8) * 72 + kb + 2 * tg]);
                af[mt][2] = ldsm_u32(&As[r * 72 + kb + 2 * tg + 8]);
                af[mt][3] = ldsm_u32(&As[(r + 8) * 72 + kb + 2 * tg + 8]);
            }
#pragma unroll
            for (int j = 0; j < 4; j++) {
                int n = wnBase + j * 8 + g;
                bf[j][0] = ldsm_u32(&Bs[n * 72 + kb + 2 * tg]);
                bf[j][1] = ldsm_u32(&Bs[n * 72 + kb + 2 * tg + 8]);
            }
#pragma unroll
            for (int mt = 0; mt < 2; mt++)
#pragma unroll
                for (int j = 0; j < 4; j++)
                    mma_f16(acc[mt][j], af[mt][0], af[mt][1], af[mt][2], af[mt][3],
                            bf[j][0], bf[j][1]);
        }
        __syncthreads();
    }

#pragma unroll
    for (int mt = 0; mt < 2; mt++) {
        int row0 = wmBase + mt * 16 + g;
#pragma unroll
        for (int j = 0; j < 4; j++) {
            int col = wnBase + j * 8 + tg * 2;
            float b0 = bp[n0 + col];
            float b1 = bp[n0 + col + 1];
            *(float2*)&O[(size_t)row0 * Cn + col] =
                make_float2(acc[mt][j][0] + b0, acc[mt][j][1] + b1);
            *(float2*)&O[(size_t)(row0 + 8) * Cn + col] =
                make_float2(acc[mt][j][2] + b0, acc[mt][j][3] + b1);
        }
    }
}

// ---------------------------------------------------------------------------

extern "C" void kernel_launch(void* const* d_in, const int* in_sizes, int n_in,
                              void* d_out, int out_size)
{
    (void)in_sizes; (void)n_in; (void)out_size;
    const float* x  = (const float*)d_in[0];
    const float* Wq = (const float*)d_in[1];
    const float* Wk = (const float*)d_in[2];
    const float* Wv = (const float*)d_in[3];
    const float* Wp = (const float*)d_in[4];
    const float* bp = (const float*)d_in[5];
    float* out = (float*)d_out;

    // resolve device-global pointers for transcvt dst offsets
    __half* hw = nullptr;
    __half* hwpt = nullptr;
    cudaGetSymbolAddress((void**)&hw, g_hw);
    cudaGetSymbolAddress((void**)&hwpt, g_hwpt);

    const size_t attn_smem = ATTN_SMEM_HALFS * sizeof(__half);  // 55296 B
    cudaFuncSetAttribute(attn_fp16,
                         cudaFuncAttributeMaxDynamicSharedMemorySize,
                         (int)attn_smem);

    conv_x_kernel<<<Bn * Tn * Cn / (256 * 4), 256>>>(x);
    transcvt_kernel<<<dim3(2, 32, 16), 256>>>(Wq, hw + 0 * Hn * Dn * Cn, Cn, Dn);
    transcvt_kernel<<<dim3(2, 32, 16), 256>>>(Wk, hw + 1 * Hn * Dn * Cn, Cn, Dn);
    transcvt_kernel<<<dim3(2, 32, 16), 256>>>(Wv, hw + 2 * Hn * Dn * Cn, Cn, Dn);
    transcvt_kernel<<<dim3(32, 32, 1), 256>>>(Wp, hwpt, Cn, Cn);

    qkv_fp16<<<dim3(32, 48), 256>>>();
    attn_fp16<<<dim3(Tn / 128, Bn * Hn), 256, attn_smem>>>();
    proj_fp16<<<dim3(32, 16), 256>>>(bp, out);
}

// round 5
// speedup vs baseline: 2.7682x; 1.7069x over previous
#include <cuda_runtime.h>
#include <cuda_fp16.h>
#include <math_constants.h>
#include <cstdint>

#define Bn 4
#define Tn 1024
#define Cn 1024
#define Hn 16
#define Dn 64

// fp16 scratch (device globals; no cudaMalloc anywhere)
__device__ __half g_hx[Bn * Tn * Cn];                  // x fp16 [4096][1024]
__device__ __half g_hw[3 * Hn * Dn * Cn];              // W^T fp16 [proj*16+h][n=64][k=1024]
__device__ __half g_hwpt[Cn * Cn];                     // Wp^T fp16 [n=1024][k=1024]
__device__ __half g_qh[Bn * Hn * Tn * Dn];
__device__ __half g_kh[Bn * Hn * Tn * Dn];
__device__ __half g_vh[Bn * Hn * Tn * Dn];
__device__ __half g_atth[Bn * Tn * Hn * Dn];           // [b][t][h*64+d] fp16

// ---------------------------------------------------------------------------
// mma / ldmatrix helpers
// ---------------------------------------------------------------------------
__device__ __forceinline__ void mma_f16(float c[4],
                                        uint32_t a0, uint32_t a1, uint32_t a2, uint32_t a3,
                                        uint32_t b0, uint32_t b1)
{
    asm volatile(
        "mma.sync.aligned.m16n8k16.row.col.f32.f16.f16.f32 "
        "{%0,%1,%2,%3}, {%4,%5,%6,%7}, {%8,%9}, {%0,%1,%2,%3};"
        : "+f"(c[0]), "+f"(c[1]), "+f"(c[2]), "+f"(c[3])
        : "r"(a0), "r"(a1), "r"(a2), "r"(a3), "r"(b0), "r"(b1));
}

__device__ __forceinline__ uint32_t smaddr(const void* p) {
    return (uint32_t)__cvta_generic_to_shared(p);
}

__device__ __forceinline__ void ldsm_x4(uint32_t& r0, uint32_t& r1,
                                        uint32_t& r2, uint32_t& r3, uint32_t addr)
{
    asm volatile("ldmatrix.sync.aligned.m8n8.x4.shared.b16 {%0,%1,%2,%3}, [%4];"
                 : "=r"(r0), "=r"(r1), "=r"(r2), "=r"(r3) : "r"(addr));
}

__device__ __forceinline__ void ldsm_x4_trans(uint32_t& r0, uint32_t& r1,
                                              uint32_t& r2, uint32_t& r3, uint32_t addr)
{
    asm volatile("ldmatrix.sync.aligned.m8n8.x4.trans.shared.b16 {%0,%1,%2,%3}, [%4];"
                 : "=r"(r0), "=r"(r1), "=r"(r2), "=r"(r3) : "r"(addr));
}

__device__ __forceinline__ uint32_t packh2(float lo, float hi) {
    __half2 h = __floats2half2_rn(lo, hi);
    return *(uint32_t*)&h;
}

// ---------------------------------------------------------------------------
// Pre-pass: convert x -> fp16
// ---------------------------------------------------------------------------
__global__ __launch_bounds__(256) void conv_x_kernel(const float* __restrict__ src)
{
    int i = (blockIdx.x * 256 + threadIdx.x) * 4;
    float4 v = *(const float4*)&src[i];
    __half2 h0 = __floats2half2_rn(v.x, v.y);
    __half2 h1 = __floats2half2_rn(v.z, v.w);
    uint2 pk = make_uint2(*(uint32_t*)&h0, *(uint32_t*)&h1);
    *(uint2*)&g_hx[i] = pk;
}

// ---------------------------------------------------------------------------
// Pre-pass: transpose + convert fp32 [nmat][R][C] -> fp16 [nmat][C][R]
// ---------------------------------------------------------------------------
__global__ __launch_bounds__(256) void transcvt_kernel(
    const float* __restrict__ src, __half* __restrict__ dst, int R, int C)
{
    __shared__ float tile[32][33];
    const int tid = threadIdx.x;
    const int m = blockIdx.z;
    src += (size_t)m * R * C;
    dst += (size_t)m * R * C;
    const int r0 = blockIdx.y * 32;
    const int c0 = blockIdx.x * 32;

    {
        int rr = tid >> 3;
        int cc = (tid & 7) * 4;
        float4 v = *(const float4*)&src[(size_t)(r0 + rr) * C + c0 + cc];
        tile[rr][cc + 0] = v.x;
        tile[rr][cc + 1] = v.y;
        tile[rr][cc + 2] = v.z;
        tile[rr][cc + 3] = v.w;
    }
    __syncthreads();
    {
        int cw = tid >> 3;
        int rw = (tid & 7) * 4;
        __half2 h0 = __floats2half2_rn(tile[rw + 0][cw], tile[rw + 1][cw]);
        __half2 h1 = __floats2half2_rn(tile[rw + 2][cw], tile[rw + 3][cw]);
        uint2 pk = make_uint2(*(uint32_t*)&h0, *(uint32_t*)&h1);
        *(uint2*)&dst[(size_t)(c0 + cw) * R + r0 + rw] = pk;
    }
}

// ---------------------------------------------------------------------------
// Kernel 1: fused QKV projection, fp16 mma + ldmatrix.
// A = g_hx [4096][1024]; B = g_hw[py] [n=64][k=1024]. Block 128x64, Kc=64.
// 8 warps = 4m x 2n, warp tile 32x32.
// ---------------------------------------------------------------------------
__global__ __launch_bounds__(256, 2) void qkv_fp16()
{
    __shared__ __align__(16) __half As[128 * 72];
    __shared__ __align__(16) __half Bs[64 * 72];

    const int tid = threadIdx.x;
    const int lane = tid & 31;
    const int warp = tid >> 5;
    const int g = lane >> 2;
    const int tg = lane & 3;
    const int wmBase = (warp & 3) * 32;
    const int wnBase = (warp >> 2) * 32;

    const int rowBase = blockIdx.x * 128;
    const int py = blockIdx.y;
    const int proj = py >> 4;
    const int h = py & 15;

    const __half* A = g_hx + (size_t)rowBase * Cn;
    const __half* B = g_hw + (size_t)py * Dn * Cn;

    __half* outp = (proj == 0 ? g_qh : (proj == 1 ? g_kh : g_vh));
    const int b  = rowBase >> 10;
    const int t0 = rowBase & (Tn - 1);
    outp += ((size_t)(b * Hn + h) * Tn + t0) * Dn;

    const int ar = tid >> 1;
    const int ah = (tid & 1) * 32;
    const int bn = tid >> 2;
    const int bh_ = (tid & 3) * 16;

    // ldmatrix per-lane addressing
    const int r16 = lane & 15;
    const int ch = (lane >> 4) * 8;

    uint4 aR[4], bR[2];
#pragma unroll
    for (int i = 0; i < 4; i++)
        aR[i] = *(const uint4*)&A[(size_t)ar * Cn + ah + i * 8];
#pragma unroll
    for (int i = 0; i < 2; i++)
        bR[i] = *(const uint4*)&B[(size_t)bn * Cn + bh_ + i * 8];

    float acc[2][4][4];
#pragma unroll
    for (int mt = 0; mt < 2; mt++)
#pragma unroll
        for (int j = 0; j < 4; j++)
#pragma unroll
            for (int e = 0; e < 4; e++) acc[mt][j][e] = 0.f;

    for (int k0 = 0; k0 < Cn; k0 += 64) {
#pragma unroll
        for (int i = 0; i < 4; i++)
            *(uint4*)&As[ar * 72 + ah + i * 8] = aR[i];
#pragma unroll
        for (int i = 0; i < 2; i++)
            *(uint4*)&Bs[bn * 72 + bh_ + i * 8] = bR[i];
        __syncthreads();

        if (k0 + 64 < Cn) {
#pragma unroll
            for (int i = 0; i < 4; i++)
                aR[i] = *(const uint4*)&A[(size_t)ar * Cn + k0 + 64 + ah + i * 8];
#pragma unroll
            for (int i = 0; i < 2; i++)
                bR[i] = *(const uint4*)&B[(size_t)bn * Cn + k0 + 64 + bh_ + i * 8];
        }

#pragma unroll
        for (int kk = 0; kk < 4; kk++) {
            const int kb = kk * 16;
            uint32_t af[2][4], bf0[4], bf1[4];
#pragma unroll
            for (int mt = 0; mt < 2; mt++)
                ldsm_x4(af[mt][0], af[mt][1], af[mt][2], af[mt][3],
                        smaddr(&As[(wmBase + mt * 16 + r16) * 72 + kb + ch]));
            ldsm_x4(bf0[0], bf0[1], bf0[2], bf0[3],
                    smaddr(&Bs[(wnBase + lane) * 72 + kb]));
            ldsm_x4(bf1[0], bf1[1], bf1[2], bf1[3],
                    smaddr(&Bs[(wnBase + lane) * 72 + kb + 8]));
#pragma unroll
            for (int mt = 0; mt < 2; mt++)
#pragma unroll
                for (int j = 0; j < 4; j++)
                    mma_f16(acc[mt][j], af[mt][0], af[mt][1], af[mt][2], af[mt][3],
                            bf0[j], bf1[j]);
        }
        __syncthreads();
    }

#pragma unroll
    for (int mt = 0; mt < 2; mt++) {
        int row0 = wmBase + mt * 16 + g;
#pragma unroll
        for (int j = 0; j < 4; j++) {
            int col = wnBase + j * 8 + tg * 2;
            __half2 lo = __floats2half2_rn(acc[mt][j][0], acc[mt][j][1]);
            __half2 hi = __floats2half2_rn(acc[mt][j][2], acc[mt][j][3]);
            *(__half2*)&outp[(size_t)row0 * Dn + col] = lo;
            *(__half2*)&outp[(size_t)(row0 + 8) * Dn + col] = hi;
        }
    }
}

// ---------------------------------------------------------------------------
// Kernel 2: causal flash attention, fp16 mma + ldmatrix.
// Q fragments hoisted to registers; P stays in registers (C layout == A layout);
// V loaded natural [s][d] and trans-ldmatrix'd as B.
// ---------------------------------------------------------------------------
#define ATTN_SMEM_HALFS (128 * 72 + 64 * 72 + 64 * 72)

__global__ __launch_bounds__(256) void attn_fp16()
{
    extern __shared__ __align__(16) __half smh[];
    __half* Qs = smh;                    // [128][72] staging only
    __half* Ks = Qs + 128 * 72;          // [64 s][72 d]
    __half* Vs = Ks + 64 * 72;           // [64 s][72 d]

    const int tid = threadIdx.x;
    const int lane = tid & 31;
    const int warp = tid >> 5;
    const int g = lane >> 2;
    const int tg = lane & 3;
    const int wm = warp * 16;
    const int qt = (int)gridDim.x - 1 - (int)blockIdx.x;
    const int bh = blockIdx.y;

    const int r16 = lane & 15;
    const int ch = (lane >> 4) * 8;

    // ---- stage Q (warp-private stripe), then hoist fragments to registers ----
    uint32_t qf[4][4];
    {
        const __half* qb = g_qh + ((size_t)bh * Tn + (size_t)qt * 128) * Dn;
        int r = tid >> 1;                 // rows 16w..16w+15 for warp w
        int hs = (tid & 1) * 32;
#pragma unroll
        for (int i = 0; i < 4; i++)
            *(uint4*)&Qs[r * 72 + hs + i * 8] =
                *(const uint4*)&qb[(size_t)r * Dn + hs + i * 8];
        __syncwarp();
#pragma unroll
        for (int kk = 0; kk < 4; kk++)
            ldsm_x4(qf[kk][0], qf[kk][1], qf[kk][2], qf[kk][3],
                    smaddr(&Qs[(wm + r16) * 72 + kk * 16 + ch]));
    }

    float m0 = -CUDART_INF_F, m1 = -CUDART_INF_F;
    float l0 = 0.f, l1 = 0.f;
    float oacc[8][4];
#pragma unroll
    for (int j = 0; j < 8; j++)
#pragma unroll
        for (int e = 0; e < 4; e++) oacc[j][e] = 0.f;

    const int row0 = qt * 128 + wm + g;
    const int row1 = row0 + 8;
    const int rowWarpMax = qt * 128 + wm + 15;

    const int nst = 2 * qt + 2;
    for (int st = 0; st < nst; st++) {
        __syncthreads();   // prior tile's mma reads done before overwrite

        // ---- load K, V natural [s][72] ----
        {
            const __half* kb_ = g_kh + ((size_t)bh * Tn + (size_t)st * 64) * Dn;
            const __half* vb_ = g_vh + ((size_t)bh * Tn + (size_t)st * 64) * Dn;
            int s = tid >> 2;
            int hs = (tid & 3) * 16;
#pragma unroll
            for (int i = 0; i < 2; i++) {
                *(uint4*)&Ks[s * 72 + hs + i * 8] =
                    *(const uint4*)&kb_[(size_t)s * Dn + hs + i * 8];
                *(uint4*)&Vs[s * 72 + hs + i * 8] =
                    *(const uint4*)&vb_[(size_t)s * Dn + hs + i * 8];
            }
        }
        __syncthreads();

        if (st * 64 > rowWarpMax) continue;

        // ---- S = Q K^T (16 x 64 per warp) ----
        float c[8][4];
#pragma unroll
        for (int j = 0; j < 8; j++)
#pragma unroll
            for (int e = 0; e < 4; e++) c[j][e] = 0.f;

#pragma unroll
        for (int kk = 0; kk < 4; kk++) {
            const int kb = kk * 16;
            uint32_t b0lo[4], b0hi[4], b1lo[4], b1hi[4];
            ldsm_x4(b0lo[0], b0lo[1], b0lo[2], b0lo[3],
                    smaddr(&Ks[lane * 72 + kb]));
            ldsm_x4(b0hi[0], b0hi[1], b0hi[2], b0hi[3],
                    smaddr(&Ks[(32 + lane) * 72 + kb]));
            ldsm_x4(b1lo[0], b1lo[1], b1lo[2], b1lo[3],
                    smaddr(&Ks[lane * 72 + kb + 8]));
            ldsm_x4(b1hi[0], b1hi[1], b1hi[2], b1hi[3],
                    smaddr(&Ks[(32 + lane) * 72 + kb + 8]));
#pragma unroll
            for (int j = 0; j < 4; j++) {
                mma_f16(c[j], qf[kk][0], qf[kk][1], qf[kk][2], qf[kk][3],
                        b0lo[j], b1lo[j]);
                mma_f16(c[j + 4], qf[kk][0], qf[kk][1], qf[kk][2], qf[kk][3],
                        b0hi[j], b1hi[j]);
            }
        }

        // ---- scale + causal mask ----
        const float scale = 0.125f;
        const bool maskt = (st * 64 + 63 > qt * 128);
#pragma unroll
        for (int j = 0; j < 8; j++) {
            int col = st * 64 + j * 8 + tg * 2;
            if (maskt) {
                c[j][0] = (col     > row0) ? -CUDART_INF_F : c[j][0] * scale;
                c[j][1] = (col + 1 > row0) ? -CUDART_INF_F : c[j][1] * scale;
                c[j][2] = (col     > row1) ? -CUDART_INF_F : c[j][2] * scale;
                c[j][3] = (col + 1 > row1) ? -CUDART_INF_F : c[j][3] * scale;
            } else {
                c[j][0] *= scale; c[j][1] *= scale;
                c[j][2] *= scale; c[j][3] *= scale;
            }
        }

        // ---- online softmax (P stays in registers) ----
        float t0 = -CUDART_INF_F, t1 = -CUDART_INF_F;
#pragma unroll
        for (int j = 0; j < 8; j++) {
            t0 = fmaxf(t0, fmaxf(c[j][0], c[j][1]));
            t1 = fmaxf(t1, fmaxf(c[j][2], c[j][3]));
        }
        t0 = fmaxf(t0, __shfl_xor_sync(0xffffffffu, t0, 1));
        t0 = fmaxf(t0, __shfl_xor_sync(0xffffffffu, t0, 2));
        t1 = fmaxf(t1, __shfl_xor_sync(0xffffffffu, t1, 1));
        t1 = fmaxf(t1, __shfl_xor_sync(0xffffffffu, t1, 2));

        float nm0 = fmaxf(m0, t0), nm1 = fmaxf(m1, t1);
        float al0 = __expf(m0 - nm0), al1 = __expf(m1 - nm1);
        float s0 = 0.f, s1 = 0.f;
#pragma unroll
        for (int j = 0; j < 8; j++) {
            c[j][0] = __expf(c[j][0] - nm0);
            c[j][1] = __expf(c[j][1] - nm0);
            c[j][2] = __expf(c[j][2] - nm1);
            c[j][3] = __expf(c[j][3] - nm1);
            s0 += c[j][0] + c[j][1];
            s1 += c[j][2] + c[j][3];
        }
        s0 += __shfl_xor_sync(0xffffffffu, s0, 1);
        s0 += __shfl_xor_sync(0xffffffffu, s0, 2);
        s1 += __shfl_xor_sync(0xffffffffu, s1, 1);
        s1 += __shfl_xor_sync(0xffffffffu, s1, 2);

        l0 = l0 * al0 + s0;  m0 = nm0;
        l1 = l1 * al1 + s1;  m1 = nm1;

#pragma unroll
        for (int j = 0; j < 8; j++) {
            oacc[j][0] *= al0; oacc[j][1] *= al0;
            oacc[j][2] *= al1; oacc[j][3] *= al1;
        }

        // ---- O += P V : P from registers, V via trans-ldmatrix ----
#pragma unroll
        for (int kk = 0; kk < 4; kk++) {
            const int kb = kk * 16;
            uint32_t a0 = packh2(c[2 * kk][0], c[2 * kk][1]);
            uint32_t a1 = packh2(c[2 * kk][2], c[2 * kk][3]);
            uint32_t a2 = packh2(c[2 * kk + 1][0], c[2 * kk + 1][1]);
            uint32_t a3 = packh2(c[2 * kk + 1][2], c[2 * kk + 1][3]);

            uint32_t v0lo[4], v0hi[4], v1lo[4], v1hi[4];
            const int srow = lane & 7;
            const int dcol = (lane >> 3) * 8;
            ldsm_x4_trans(v0lo[0], v0lo[1], v0lo[2], v0lo[3],
                          smaddr(&Vs[(kb + srow) * 72 + dcol]));
            ldsm_x4_trans(v0hi[0], v0hi[1], v0hi[2], v0hi[3],
                          smaddr(&Vs[(kb + srow) * 72 + dcol + 32]));
            ldsm_x4_trans(v1lo[0], v1lo[1], v1lo[2], v1lo[3],
                          smaddr(&Vs[(kb + 8 + srow) * 72 + dcol]));
            ldsm_x4_trans(v1hi[0], v1hi[1], v1hi[2], v1hi[3],
                          smaddr(&Vs[(kb + 8 + srow) * 72 + dcol + 32]));
#pragma unroll
            for (int j = 0; j < 4; j++) {
                mma_f16(oacc[j], a0, a1, a2, a3, v0lo[j], v1lo[j]);
                mma_f16(oacc[j + 4], a0, a1, a2, a3, v0hi[j], v1hi[j]);
            }
        }
    }

    // ---- epilogue -> g_atth [b][t][h*64+d] fp16 ----
    const int b = bh >> 4, h = bh & 15;
    __half* ob = g_atth + ((size_t)b * Tn + (size_t)qt * 128) * (Hn * Dn) + h * Dn;
    float inv0 = 1.f / l0, inv1 = 1.f / l1;
#pragma unroll
    for (int j = 0; j < 8; j++) {
        int col = j * 8 + tg * 2;
        *(__half2*)&ob[(size_t)(wm + g) * (Hn * Dn) + col] =
            __floats2half2_rn(oacc[j][0] * inv0, oacc[j][1] * inv0);
        *(__half2*)&ob[(size_t)(wm + g + 8) * (Hn * Dn) + col] =
            __floats2half2_rn(oacc[j][2] * inv1, oacc[j][3] * inv1);
    }
}

// ---------------------------------------------------------------------------
// Kernel 3: output projection, fp16 mma + ldmatrix.
// ---------------------------------------------------------------------------
__global__ __launch_bounds__(256, 2) void proj_fp16(
    const float* __restrict__ bp, float* __restrict__ out)
{
    __shared__ __align__(16) __half As[128 * 72];
    __shared__ __align__(16) __half Bs[64 * 72];

    const int tid = threadIdx.x;
    const int lane = tid & 31;
    const int warp = tid >> 5;
    const int g = lane >> 2;
    const int tg = lane & 3;
    const int wmBase = (warp & 3) * 32;
    const int wnBase = (warp >> 2) * 32;

    const int rowBase = blockIdx.x * 128;
    const int n0 = blockIdx.y * 64;

    const __half* A = g_atth + (size_t)rowBase * Cn;
    const __half* B = g_hwpt + (size_t)n0 * Cn;
    float* O = out + (size_t)rowBase * Cn + n0;

    const int ar = tid >> 1;
    const int ah = (tid & 1) * 32;
    const int bn = tid >> 2;
    const int bh_ = (tid & 3) * 16;

    const int r16 = lane & 15;
    const int ch = (lane >> 4) * 8;

    uint4 aR[4], bR[2];
#pragma unroll
    for (int i = 0; i < 4; i++)
        aR[i] = *(const uint4*)&A[(size_t)ar * Cn + ah + i * 8];
#pragma unroll
    for (int i = 0; i < 2; i++)
        bR[i] = *(const uint4*)&B[(size_t)bn * Cn + bh_ + i * 8];

    float acc[2][4][4];
#pragma unroll
    for (int mt = 0; mt < 2; mt++)
#pragma unroll
        for (int j = 0; j < 4; j++)
#pragma unroll
            for (int e = 0; e < 4; e++) acc[mt][j][e] = 0.f;

    for (int k0 = 0; k0 < Cn; k0 += 64) {
#pragma unroll
        for (int i = 0; i < 4; i++)
            *(uint4*)&As[ar * 72 + ah + i * 8] = aR[i];
#pragma unroll
        for (int i = 0; i < 2; i++)
            *(uint4*)&Bs[bn * 72 + bh_ + i * 8] = bR[i];
        __syncthreads();

        if (k0 + 64 < Cn) {
#pragma unroll
            for (int i = 0; i < 4; i++)
                aR[i] = *(const uint4*)&A[(size_t)ar * Cn + k0 + 64 + ah + i * 8];
#pragma unroll
            for (int i = 0; i < 2; i++)
                bR[i] = *(const uint4*)&B[(size_t)bn * Cn + k0 + 64 + bh_ + i * 8];
        }

#pragma unroll
        for (int kk = 0; kk < 4; kk++) {
            const int kb = kk * 16;
            uint32_t af[2][4], bf0[4], bf1[4];
#pragma unroll
            for (int mt = 0; mt < 2; mt++)
                ldsm_x4(af[mt][0], af[mt][1], af[mt][2], af[mt][3],
                        smaddr(&As[(wmBase + mt * 16 + r16) * 72 + kb + ch]));
            ldsm_x4(bf0[0], bf0[1], bf0[2], bf0[3],
                    smaddr(&Bs[(wnBase + lane) * 72 + kb]));
            ldsm_x4(bf1[0], bf1[1], bf1[2], bf1[3],
                    smaddr(&Bs[(wnBase + lane) * 72 + kb + 8]));
#pragma unroll
            for (int mt = 0; mt < 2; mt++)
#pragma unroll
                for (int j = 0; j < 4; j++)
                    mma_f16(acc[mt][j], af[mt][0], af[mt][1], af[mt][2], af[mt][3],
                            bf0[j], bf1[j]);
        }
        __syncthreads();
    }

#pragma unroll
    for (int mt = 0; mt < 2; mt++) {
        int row0 = wmBase + mt * 16 + g;
#pragma unroll
        for (int j = 0; j < 4; j++) {
            int col = wnBase + j * 8 + tg * 2;
            float b0 = bp[n0 + col];
            float b1 = bp[n0 + col + 1];
            *(float2*)&O[(size_t)row0 * Cn + col] =
                make_float2(acc[mt][j][0] + b0, acc[mt][j][1] + b1);
            *(float2*)&O[(size_t)(row0 + 8) * Cn + col] =
                make_float2(acc[mt][j][2] + b0, acc[mt][j][3] + b1);
        }
    }
}

// ---------------------------------------------------------------------------

extern "C" void kernel_launch(void* const* d_in, const int* in_sizes, int n_in,
                              void* d_out, int out_size)
{
    (void)in_sizes; (void)n_in; (void)out_size;
    const float* x  = (const float*)d_in[0];
    const float* Wq = (const float*)d_in[1];
    const float* Wk = (const float*)d_in[2];
    const float* Wv = (const float*)d_in[3];
    const float* Wp = (const float*)d_in[4];
    const float* bp = (const float*)d_in[5];
    float* out = (float*)d_out;

    __half* hw = nullptr;
    __half* hwpt = nullptr;
    cudaGetSymbolAddress((void**)&hw, g_hw);
    cudaGetSymbolAddress((void**)&hwpt, g_hwpt);

    const size_t attn_smem = ATTN_SMEM_HALFS * sizeof(__half);  // 36864 B
    cudaFuncSetAttribute(attn_fp16,
                         cudaFuncAttributeMaxDynamicSharedMemorySize,
                         (int)attn_smem);

    conv_x_kernel<<<Bn * Tn * Cn / (256 * 4), 256>>>(x);
    transcvt_kernel<<<dim3(2, 32, 16), 256>>>(Wq, hw + 0 * Hn * Dn * Cn, Cn, Dn);
    transcvt_kernel<<<dim3(2, 32, 16), 256>>>(Wk, hw + 1 * Hn * Dn * Cn, Cn, Dn);
    transcvt_kernel<<<dim3(2, 32, 16), 256>>>(Wv, hw + 2 * Hn * Dn * Cn, Cn, Dn);
    transcvt_kernel<<<dim3(32, 32, 1), 256>>>(Wp, hwpt, Cn, Cn);

    qkv_fp16<<<dim3(32, 48), 256>>>();
    attn_fp16<<<dim3(Tn / 128, Bn * Hn), 256, attn_smem>>>();
    proj_fp16<<<dim3(32, 16), 256>>>(bp, out);
}

// round 6
// speedup vs baseline: 2.9185x; 1.0543x over previous
#include <cuda_runtime.h>
#include <cuda_fp16.h>
#include <math_constants.h>
#include <cstdint>

#define Bn 4
#define Tn 1024
#define Cn 1024
#define Hn 16
#define Dn 64

// fp16 scratch (device globals; no cudaMalloc anywhere)
__device__ __half g_hx[Bn * Tn * Cn];                  // x fp16 [4096][1024]
__device__ __half g_hw[3 * Hn * Dn * Cn];              // W^T fp16 [proj*16+h][n=64][k=1024]
__device__ __half g_hwpt[Cn * Cn];                     // Wp^T fp16 [n=1024][k=1024]
__device__ __half g_qh[Bn * Hn * Tn * Dn];
__device__ __half g_kh[Bn * Hn * Tn * Dn];
__device__ __half g_vh[Bn * Hn * Tn * Dn];
__device__ __half g_atth[Bn * Tn * Hn * Dn];           // [b][t][h*64+d] fp16

// ---------------------------------------------------------------------------
// mma / ldmatrix helpers
// ---------------------------------------------------------------------------
__device__ __forceinline__ void mma_f16(float c[4],
                                        uint32_t a0, uint32_t a1, uint32_t a2, uint32_t a3,
                                        uint32_t b0, uint32_t b1)
{
    asm volatile(
        "mma.sync.aligned.m16n8k16.row.col.f32.f16.f16.f32 "
        "{%0,%1,%2,%3}, {%4,%5,%6,%7}, {%8,%9}, {%0,%1,%2,%3};"
        : "+f"(c[0]), "+f"(c[1]), "+f"(c[2]), "+f"(c[3])
        : "r"(a0), "r"(a1), "r"(a2), "r"(a3), "r"(b0), "r"(b1));
}

__device__ __forceinline__ uint32_t smaddr(const void* p) {
    return (uint32_t)__cvta_generic_to_shared(p);
}

__device__ __forceinline__ void ldsm_x4(uint32_t& r0, uint32_t& r1,
                                        uint32_t& r2, uint32_t& r3, uint32_t addr)
{
    asm volatile("ldmatrix.sync.aligned.m8n8.x4.shared.b16 {%0,%1,%2,%3}, [%4];"
                 : "=r"(r0), "=r"(r1), "=r"(r2), "=r"(r3) : "r"(addr));
}

__device__ __forceinline__ void ldsm_x4_trans(uint32_t& r0, uint32_t& r1,
                                              uint32_t& r2, uint32_t& r3, uint32_t addr)
{
    asm volatile("ldmatrix.sync.aligned.m8n8.x4.trans.shared.b16 {%0,%1,%2,%3}, [%4];"
                 : "=r"(r0), "=r"(r1), "=r"(r2), "=r"(r3) : "r"(addr));
}

__device__ __forceinline__ uint32_t packh2(float lo, float hi) {
    __half2 h = __floats2half2_rn(lo, hi);
    return *(uint32_t*)&h;
}

// ---------------------------------------------------------------------------
// Pre-pass: convert x -> fp16
// ---------------------------------------------------------------------------
__global__ __launch_bounds__(256) void conv_x_kernel(const float* __restrict__ src)
{
    int i = (blockIdx.x * 256 + threadIdx.x) * 4;
    float4 v = *(const float4*)&src[i];
    __half2 h0 = __floats2half2_rn(v.x, v.y);
    __half2 h1 = __floats2half2_rn(v.z, v.w);
    uint2 pk = make_uint2(*(uint32_t*)&h0, *(uint32_t*)&h1);
    *(uint2*)&g_hx[i] = pk;
}

// ---------------------------------------------------------------------------
// Pre-pass: transpose + convert Wq/Wk/Wv fp32 [16][1024][64] -> g_hw fp16 [48][64][1024]
// One launch: blockIdx.z = 0..47 picks (proj, head).
// ---------------------------------------------------------------------------
__global__ __launch_bounds__(256) void transcvt_w3(
    const float* __restrict__ Wq, const float* __restrict__ Wk,
    const float* __restrict__ Wv)
{
    __shared__ float tile[32][33];
    const int tid = threadIdx.x;
    const int m = blockIdx.z;                 // 0..47
    const float* src = (m < 16 ? Wq : (m < 32 ? Wk : Wv)) + (size_t)(m & 15) * Cn * Dn;
    __half* dst = g_hw + (size_t)m * Dn * Cn;
    const int r0 = blockIdx.y * 32;           // 0..992 (R = 1024)
    const int c0 = blockIdx.x * 32;           // 0 or 32 (C = 64)

    {
        int rr = tid >> 3;
        int cc = (tid & 7) * 4;
        float4 v = *(const float4*)&src[(size_t)(r0 + rr) * Dn + c0 + cc];
        tile[rr][cc + 0] = v.x;
        tile[rr][cc + 1] = v.y;
        tile[rr][cc + 2] = v.z;
        tile[rr][cc + 3] = v.w;
    }
    __syncthreads();
    {
        int cw = tid >> 3;
        int rw = (tid & 7) * 4;
        __half2 h0 = __floats2half2_rn(tile[rw + 0][cw], tile[rw + 1][cw]);
        __half2 h1 = __floats2half2_rn(tile[rw + 2][cw], tile[rw + 3][cw]);
        uint2 pk = make_uint2(*(uint32_t*)&h0, *(uint32_t*)&h1);
        *(uint2*)&dst[(size_t)(c0 + cw) * Cn + r0 + rw] = pk;
    }
}

// ---------------------------------------------------------------------------
// Pre-pass: transpose + convert Wp [1024][1024] -> g_hwpt [n][k] fp16
// ---------------------------------------------------------------------------
__global__ __launch_bounds__(256) void transcvt_kernel(
    const float* __restrict__ src, __half* __restrict__ dst, int R, int C)
{
    __shared__ float tile[32][33];
    const int tid = threadIdx.x;
    const int r0 = blockIdx.y * 32;
    const int c0 = blockIdx.x * 32;

    {
        int rr = tid >> 3;
        int cc = (tid & 7) * 4;
        float4 v = *(const float4*)&src[(size_t)(r0 + rr) * C + c0 + cc];
        tile[rr][cc + 0] = v.x;
        tile[rr][cc + 1] = v.y;
        tile[rr][cc + 2] = v.z;
        tile[rr][cc + 3] = v.w;
    }
    __syncthreads();
    {
        int cw = tid >> 3;
        int rw = (tid & 7) * 4;
        __half2 h0 = __floats2half2_rn(tile[rw + 0][cw], tile[rw + 1][cw]);
        __half2 h1 = __floats2half2_rn(tile[rw + 2][cw], tile[rw + 3][cw]);
        uint2 pk = make_uint2(*(uint32_t*)&h0, *(uint32_t*)&h1);
        *(uint2*)&dst[(size_t)(c0 + cw) * R + r0 + rw] = pk;
    }
}

// ---------------------------------------------------------------------------
// Kernel 1: fused QKV projection, fp16 mma + ldmatrix. Block tile 128x128
// (one block = 2 heads), Kc=64. 8 warps = 4m x 2n, warp tile 32x64.
// grid (32, 24): y = proj*8 + head-pair.
// ---------------------------------------------------------------------------
__global__ __launch_bounds__(256) void qkv_fp16()
{
    __shared__ __align__(16) __half As[128 * 72];
    __shared__ __align__(16) __half Bs[128 * 72];

    const int tid = threadIdx.x;
    const int lane = tid & 31;
    const int warp = tid >> 5;
    const int g = lane >> 2;
    const int tg = lane & 3;
    const int wmBase = (warp & 3) * 32;
    const int wnBase = (warp >> 2) * 64;

    const int rowBase = blockIdx.x * 128;
    const int py = blockIdx.y;
    const int proj = py >> 3;
    const int hp = py & 7;                    // head pair

    const __half* A = g_hx + (size_t)rowBase * Cn;
    const __half* B = g_hw + (size_t)(proj * Hn + hp * 2) * Dn * Cn;  // 128 n-rows

    __half* outbase = (proj == 0 ? g_qh : (proj == 1 ? g_kh : g_vh));
    const int b  = rowBase >> 10;
    const int t0 = rowBase & (Tn - 1);

    const int ar = tid >> 1;
    const int ah = (tid & 1) * 32;

    const int r16 = lane & 15;
    const int ch = (lane >> 4) * 8;

    uint4 aR[4], bR[4];
#pragma unroll
    for (int i = 0; i < 4; i++) {
        aR[i] = *(const uint4*)&A[(size_t)ar * Cn + ah + i * 8];
        bR[i] = *(const uint4*)&B[(size_t)ar * Cn + ah + i * 8];
    }

    float acc[2][8][4];
#pragma unroll
    for (int mt = 0; mt < 2; mt++)
#pragma unroll
        for (int j = 0; j < 8; j++)
#pragma unroll
            for (int e = 0; e < 4; e++) acc[mt][j][e] = 0.f;

    for (int k0 = 0; k0 < Cn; k0 += 64) {
#pragma unroll
        for (int i = 0; i < 4; i++) {
            *(uint4*)&As[ar * 72 + ah + i * 8] = aR[i];
            *(uint4*)&Bs[ar * 72 + ah + i * 8] = bR[i];
        }
        __syncthreads();

        if (k0 + 64 < Cn) {
#pragma unroll
            for (int i = 0; i < 4; i++) {
                aR[i] = *(const uint4*)&A[(size_t)ar * Cn + k0 + 64 + ah + i * 8];
                bR[i] = *(const uint4*)&B[(size_t)ar * Cn + k0 + 64 + ah + i * 8];
            }
        }

#pragma unroll
        for (int kk = 0; kk < 4; kk++) {
            const int kb = kk * 16;
            uint32_t af[2][4], bf0[8], bf1[8];
#pragma unroll
            for (int mt = 0; mt < 2; mt++)
                ldsm_x4(af[mt][0], af[mt][1], af[mt][2], af[mt][3],
                        smaddr(&As[(wmBase + mt * 16 + r16) * 72 + kb + ch]));
            ldsm_x4(bf0[0], bf0[1], bf0[2], bf0[3],
                    smaddr(&Bs[(wnBase + lane) * 72 + kb]));
            ldsm_x4(bf0[4], bf0[5], bf0[6], bf0[7],
                    smaddr(&Bs[(wnBase + 32 + lane) * 72 + kb]));
            ldsm_x4(bf1[0], bf1[1], bf1[2], bf1[3],
                    smaddr(&Bs[(wnBase + lane) * 72 + kb + 8]));
            ldsm_x4(bf1[4], bf1[5], bf1[6], bf1[7],
                    smaddr(&Bs[(wnBase + 32 + lane) * 72 + kb + 8]));
#pragma unroll
            for (int mt = 0; mt < 2; mt++)
#pragma unroll
                for (int j = 0; j < 8; j++)
                    mma_f16(acc[mt][j], af[mt][0], af[mt][1], af[mt][2], af[mt][3],
                            bf0[j], bf1[j]);
        }
        __syncthreads();
    }

    // epilogue: column col (0..127) -> head hp*2 + (col>>6), d = col&63
#pragma unroll
    for (int mt = 0; mt < 2; mt++) {
        int row0 = wmBase + mt * 16 + g;
#pragma unroll
        for (int j = 0; j < 8; j++) {
            int col = wnBase + j * 8 + tg * 2;
            int h = hp * 2 + (col >> 6);
            int d = col & 63;
            __half* ob = outbase + ((size_t)(b * Hn + h) * Tn + t0) * Dn + d;
            *(__half2*)&ob[(size_t)row0 * Dn] =
                __floats2half2_rn(acc[mt][j][0], acc[mt][j][1]);
            *(__half2*)&ob[(size_t)(row0 + 8) * Dn] =
                __floats2half2_rn(acc[mt][j][2], acc[mt][j][3]);
        }
    }
}

// ---------------------------------------------------------------------------
// Kernel 2: causal flash attention, fp16 mma + ldmatrix, register-prefetched
// K/V tiles. Q fragments in registers; P stays in registers.
// ---------------------------------------------------------------------------
#define ATTN_SMEM_HALFS (128 * 72 + 64 * 72 + 64 * 72)

__global__ __launch_bounds__(256) void attn_fp16()
{
    extern __shared__ __align__(16) __half smh[];
    __half* Qs = smh;                    // [128][72] staging only
    __half* Ks = Qs + 128 * 72;          // [64 s][72 d]
    __half* Vs = Ks + 64 * 72;           // [64 s][72 d]

    const int tid = threadIdx.x;
    const int lane = tid & 31;
    const int warp = tid >> 5;
    const int g = lane >> 2;
    const int tg = lane & 3;
    const int wm = warp * 16;
    const int qt = (int)gridDim.x - 1 - (int)blockIdx.x;
    const int bh = blockIdx.y;

    const int r16 = lane & 15;
    const int ch = (lane >> 4) * 8;

    // ---- stage Q (warp-private stripe), hoist fragments to registers ----
    uint32_t qf[4][4];
    {
        const __half* qb = g_qh + ((size_t)bh * Tn + (size_t)qt * 128) * Dn;
        int r = tid >> 1;
        int hs = (tid & 1) * 32;
#pragma unroll
        for (int i = 0; i < 4; i++)
            *(uint4*)&Qs[r * 72 + hs + i * 8] =
                *(const uint4*)&qb[(size_t)r * Dn + hs + i * 8];
        __syncwarp();
#pragma unroll
        for (int kk = 0; kk < 4; kk++)
            ldsm_x4(qf[kk][0], qf[kk][1], qf[kk][2], qf[kk][3],
                    smaddr(&Qs[(wm + r16) * 72 + kk * 16 + ch]));
    }

    float m0 = -CUDART_INF_F, m1 = -CUDART_INF_F;
    float l0 = 0.f, l1 = 0.f;
    float oacc[8][4];
#pragma unroll
    for (int j = 0; j < 8; j++)
#pragma unroll
        for (int e = 0; e < 4; e++) oacc[j][e] = 0.f;

    const int row0 = qt * 128 + wm + g;
    const int row1 = row0 + 8;
    const int rowWarpMax = qt * 128 + wm + 15;

    const __half* kbase = g_kh + (size_t)bh * Tn * Dn;
    const __half* vbase = g_vh + (size_t)bh * Tn * Dn;
    const int sr = tid >> 2;              // 0..63 (s row)
    const int sh = (tid & 3) * 16;        // half offset

    // prologue: prefetch tile 0
    uint4 kR[2], vR[2];
#pragma unroll
    for (int i = 0; i < 2; i++) {
        kR[i] = *(const uint4*)&kbase[(size_t)sr * Dn + sh + i * 8];
        vR[i] = *(const uint4*)&vbase[(size_t)sr * Dn + sh + i * 8];
    }

    const int nst = 2 * qt + 2;
    for (int st = 0; st < nst; st++) {
        __syncthreads();   // prior tile's mma reads done before overwrite
#pragma unroll
        for (int i = 0; i < 2; i++) {
            *(uint4*)&Ks[sr * 72 + sh + i * 8] = kR[i];
            *(uint4*)&Vs[sr * 72 + sh + i * 8] = vR[i];
        }
        __syncthreads();

        // prefetch next tile while computing this one
        if (st + 1 < nst) {
            const __half* kn = kbase + (size_t)(st + 1) * 64 * Dn;
            const __half* vn = vbase + (size_t)(st + 1) * 64 * Dn;
#pragma unroll
            for (int i = 0; i < 2; i++) {
                kR[i] = *(const uint4*)&kn[(size_t)sr * Dn + sh + i * 8];
                vR[i] = *(const uint4*)&vn[(size_t)sr * Dn + sh + i * 8];
            }
        }

        if (st * 64 > rowWarpMax) continue;

        // ---- S = Q K^T (16 x 64 per warp) ----
        float c[8][4];
#pragma unroll
        for (int j = 0; j < 8; j++)
#pragma unroll
            for (int e = 0; e < 4; e++) c[j][e] = 0.f;

#pragma unroll
        for (int kk = 0; kk < 4; kk++) {
            const int kb = kk * 16;
            uint32_t b0lo[4], b0hi[4], b1lo[4], b1hi[4];
            ldsm_x4(b0lo[0], b0lo[1], b0lo[2], b0lo[3],
                    smaddr(&Ks[lane * 72 + kb]));
            ldsm_x4(b0hi[0], b0hi[1], b0hi[2], b0hi[3],
                    smaddr(&Ks[(32 + lane) * 72 + kb]));
            ldsm_x4(b1lo[0], b1lo[1], b1lo[2], b1lo[3],
                    smaddr(&Ks[lane * 72 + kb + 8]));
            ldsm_x4(b1hi[0], b1hi[1], b1hi[2], b1hi[3],
                    smaddr(&Ks[(32 + lane) * 72 + kb + 8]));
#pragma unroll
            for (int j = 0; j < 4; j++) {
                mma_f16(c[j], qf[kk][0], qf[kk][1], qf[kk][2], qf[kk][3],
                        b0lo[j], b1lo[j]);
                mma_f16(c[j + 4], qf[kk][0], qf[kk][1], qf[kk][2], qf[kk][3],
                        b0hi[j], b1hi[j]);
            }
        }

        // ---- scale + causal mask ----
        const float scale = 0.125f;
        const bool maskt = (st * 64 + 63 > qt * 128);
#pragma unroll
        for (int j = 0; j < 8; j++) {
            int col = st * 64 + j * 8 + tg * 2;
            if (maskt) {
                c[j][0] = (col     > row0) ? -CUDART_INF_F : c[j][0] * scale;
                c[j][1] = (col + 1 > row0) ? -CUDART_INF_F : c[j][1] * scale;
                c[j][2] = (col     > row1) ? -CUDART_INF_F : c[j][2] * scale;
                c[j][3] = (col + 1 > row1) ? -CUDART_INF_F : c[j][3] * scale;
            } else {
                c[j][0] *= scale; c[j][1] *= scale;
                c[j][2] *= scale; c[j][3] *= scale;
            }
        }

        // ---- online softmax (P stays in registers) ----
        float t0 = -CUDART_INF_F, t1 = -CUDART_INF_F;
#pragma unroll
        for (int j = 0; j < 8; j++) {
            t0 = fmaxf(t0, fmaxf(c[j][0], c[j][1]));
            t1 = fmaxf(t1, fmaxf(c[j][2], c[j][3]));
        }
        t0 = fmaxf(t0, __shfl_xor_sync(0xffffffffu, t0, 1));
        t0 = fmaxf(t0, __shfl_xor_sync(0xffffffffu, t0, 2));
        t1 = fmaxf(t1, __shfl_xor_sync(0xffffffffu, t1, 1));
        t1 = fmaxf(t1, __shfl_xor_sync(0xffffffffu, t1, 2));

        float nm0 = fmaxf(m0, t0), nm1 = fmaxf(m1, t1);
        float al0 = __expf(m0 - nm0), al1 = __expf(m1 - nm1);
        float s0 = 0.f, s1 = 0.f;
#pragma unroll
        for (int j = 0; j < 8; j++) {
            c[j][0] = __expf(c[j][0] - nm0);
            c[j][1] = __expf(c[j][1] - nm0);
            c[j][2] = __expf(c[j][2] - nm1);
            c[j][3] = __expf(c[j][3] - nm1);
            s0 += c[j][0] + c[j][1];
            s1 += c[j][2] + c[j][3];
        }
        s0 += __shfl_xor_sync(0xffffffffu, s0, 1);
        s0 += __shfl_xor_sync(0xffffffffu, s0, 2);
        s1 += __shfl_xor_sync(0xffffffffu, s1, 1);
        s1 += __shfl_xor_sync(0xffffffffu, s1, 2);

        l0 = l0 * al0 + s0;  m0 = nm0;
        l1 = l1 * al1 + s1;  m1 = nm1;

#pragma unroll
        for (int j = 0; j < 8; j++) {
            oacc[j][0] *= al0; oacc[j][1] *= al0;
            oacc[j][2] *= al1; oacc[j][3] *= al1;
        }

        // ---- O += P V : P from registers, V via trans-ldmatrix ----
#pragma unroll
        for (int kk = 0; kk < 4; kk++) {
            const int kb = kk * 16;
            uint32_t a0 = packh2(c[2 * kk][0], c[2 * kk][1]);
            uint32_t a1 = packh2(c[2 * kk][2], c[2 * kk][3]);
            uint32_t a2 = packh2(c[2 * kk + 1][0], c[2 * kk + 1][1]);
            uint32_t a3 = packh2(c[2 * kk + 1][2], c[2 * kk + 1][3]);

            uint32_t v0lo[4], v0hi[4], v1lo[4], v1hi[4];
            const int srow = lane & 7;
            const int dcol = (lane >> 3) * 8;
            ldsm_x4_trans(v0lo[0], v0lo[1], v0lo[2], v0lo[3],
                          smaddr(&Vs[(kb + srow) * 72 + dcol]));
            ldsm_x4_trans(v0hi[0], v0hi[1], v0hi[2], v0hi[3],
                          smaddr(&Vs[(kb + srow) * 72 + dcol + 32]));
            ldsm_x4_trans(v1lo[0], v1lo[1], v1lo[2], v1lo[3],
                          smaddr(&Vs[(kb + 8 + srow) * 72 + dcol]));
            ldsm_x4_trans(v1hi[0], v1hi[1], v1hi[2], v1hi[3],
                          smaddr(&Vs[(kb + 8 + srow) * 72 + dcol + 32]));
#pragma unroll
            for (int j = 0; j < 4; j++) {
                mma_f16(oacc[j], a0, a1, a2, a3, v0lo[j], v1lo[j]);
                mma_f16(oacc[j + 4], a0, a1, a2, a3, v0hi[j], v1hi[j]);
            }
        }
    }

    // ---- epilogue -> g_atth [b][t][h*64+d] fp16 ----
    const int b = bh >> 4, h = bh & 15;
    __half* ob = g_atth + ((size_t)b * Tn + (size_t)qt * 128) * (Hn * Dn) + h * Dn;
    float inv0 = 1.f / l0, inv1 = 1.f / l1;
#pragma unroll
    for (int j = 0; j < 8; j++) {
        int col = j * 8 + tg * 2;
        *(__half2*)&ob[(size_t)(wm + g) * (Hn * Dn) + col] =
            __floats2half2_rn(oacc[j][0] * inv0, oacc[j][1] * inv0);
        *(__half2*)&ob[(size_t)(wm + g + 8) * (Hn * Dn) + col] =
            __floats2half2_rn(oacc[j][2] * inv1, oacc[j][3] * inv1);
    }
}

// ---------------------------------------------------------------------------
// Kernel 3: output projection, fp16 mma + ldmatrix. Block tile 128x128.
// ---------------------------------------------------------------------------
__global__ __launch_bounds__(256) void proj_fp16(
    const float* __restrict__ bp, float* __restrict__ out)
{
    __shared__ __align__(16) __half As[128 * 72];
    __shared__ __align__(16) __half Bs[128 * 72];

    const int tid = threadIdx.x;
    const int lane = tid & 31;
    const int warp = tid >> 5;
    const int g = lane >> 2;
    const int tg = lane & 3;
    const int wmBase = (warp & 3) * 32;
    const int wnBase = (warp >> 2) * 64;

    const int rowBase = blockIdx.x * 128;
    const int n0 = blockIdx.y * 128;

    const __half* A = g_atth + (size_t)rowBase * Cn;
    const __half* B = g_hwpt + (size_t)n0 * Cn;
    float* O = out + (size_t)rowBase * Cn + n0;

    const int ar = tid >> 1;
    const int ah = (tid & 1) * 32;

    const int r16 = lane & 15;
    const int ch = (lane >> 4) * 8;

    uint4 aR[4], bR[4];
#pragma unroll
    for (int i = 0; i < 4; i++) {
        aR[i] = *(const uint4*)&A[(size_t)ar * Cn + ah + i * 8];
        bR[i] = *(const uint4*)&B[(size_t)ar * Cn + ah + i * 8];
    }

    float acc[2][8][4];
#pragma unroll
    for (int mt = 0; mt < 2; mt++)
#pragma unroll
        for (int j = 0; j < 8; j++)
#pragma unroll
            for (int e = 0; e < 4; e++) acc[mt][j][e] = 0.f;

    for (int k0 = 0; k0 < Cn; k0 += 64) {
#pragma unroll
        for (int i = 0; i < 4; i++) {
            *(uint4*)&As[ar * 72 + ah + i * 8] = aR[i];
            *(uint4*)&Bs[ar * 72 + ah + i * 8] = bR[i];
        }
        __syncthreads();

        if (k0 + 64 < Cn) {
#pragma unroll
            for (int i = 0; i < 4; i++) {
                aR[i] = *(const uint4*)&A[(size_t)ar * Cn + k0 + 64 + ah + i * 8];
                bR[i] = *(const uint4*)&B[(size_t)ar * Cn + k0 + 64 + ah + i * 8];
            }
        }

#pragma unroll
        for (int kk = 0; kk < 4; kk++) {
            const int kb = kk * 16;
            uint32_t af[2][4], bf0[8], bf1[8];
#pragma unroll
            for (int mt = 0; mt < 2; mt++)
                ldsm_x4(af[mt][0], af[mt][1], af[mt][2], af[mt][3],
                        smaddr(&As[(wmBase + mt * 16 + r16) * 72 + kb + ch]));
            ldsm_x4(bf0[0], bf0[1], bf0[2], bf0[3],
                    smaddr(&Bs[(wnBase + lane) * 72 + kb]));
            ldsm_x4(bf0[4], bf0[5], bf0[6], bf0[7],
                    smaddr(&Bs[(wnBase + 32 + lane) * 72 + kb]));
            ldsm_x4(bf1[0], bf1[1], bf1[2], bf1[3],
                    smaddr(&Bs[(wnBase + lane) * 72 + kb + 8]));
            ldsm_x4(bf1[4], bf1[5], bf1[6], bf1[7],
                    smaddr(&Bs[(wnBase + 32 + lane) * 72 + kb + 8]));
#pragma unroll
            for (int mt = 0; mt < 2; mt++)
#pragma unroll
                for (int j = 0; j < 8; j++)
                    mma_f16(acc[mt][j], af[mt][0], af[mt][1], af[mt][2], af[mt][3],
                            bf0[j], bf1[j]);
        }
        __syncthreads();
    }

#pragma unroll
    for (int mt = 0; mt < 2; mt++) {
        int row0 = wmBase + mt * 16 + g;
#pragma unroll
        for (int j = 0; j < 8; j++) {
            int col = wnBase + j * 8 + tg * 2;
            float b0 = bp[n0 + col];
            float b1 = bp[n0 + col + 1];
            *(float2*)&O[(size_t)row0 * Cn + col] =
                make_float2(acc[mt][j][0] + b0, acc[mt][j][1] + b1);
            *(float2*)&O[(size_t)(row0 + 8) * Cn + col] =
                make_float2(acc[mt][j][2] + b0, acc[mt][j][3] + b1);
        }
    }
}

// ---------------------------------------------------------------------------

extern "C" void kernel_launch(void* const* d_in, const int* in_sizes, int n_in,
                              void* d_out, int out_size)
{
    (void)in_sizes; (void)n_in; (void)out_size;
    const float* x  = (const float*)d_in[0];
    const float* Wq = (const float*)d_in[1];
    const float* Wk = (const float*)d_in[2];
    const float* Wv = (const float*)d_in[3];
    const float* Wp = (const float*)d_in[4];
    const float* bp = (const float*)d_in[5];
    float* out = (float*)d_out;

    __half* hwpt = nullptr;
    cudaGetSymbolAddress((void**)&hwpt, g_hwpt);

    const size_t attn_smem = ATTN_SMEM_HALFS * sizeof(__half);  // 36864 B
    cudaFuncSetAttribute(attn_fp16,
                         cudaFuncAttributeMaxDynamicSharedMemorySize,
                         (int)attn_smem);

    conv_x_kernel<<<Bn * Tn * Cn / (256 * 4), 256>>>(x);
    transcvt_w3<<<dim3(2, 32, 48), 256>>>(Wq, Wk, Wv);
    transcvt_kernel<<<dim3(32, 32, 1), 256>>>(Wp, hwpt, Cn, Cn);

    qkv_fp16<<<dim3(32, 24), 256>>>();
    attn_fp16<<<dim3(Tn / 128, Bn * Hn), 256, attn_smem>>>();
    proj_fp16<<<dim3(32, 8), 256>>>(bp, out);
}

// round 9
// speedup vs baseline: 3.0632x; 1.0496x over previous
#include <cuda_runtime.h>
#include <cuda_fp16.h>
#include <math_constants.h>
#include <cstdint>

#define Bn 4
#define Tn 1024
#define Cn 1024
#define Hn 16
#define Dn 64

// fp16 scratch (device globals; no cudaMalloc anywhere)
__device__ __half g_hx[Bn * Tn * Cn];                  // x fp16 [4096][1024]
__device__ __half g_hw[3 * Hn * Dn * Cn];              // W^T fp16 [proj*16+h][n=64][k=1024]
__device__ __half g_hwpt[Cn * Cn];                     // Wp^T fp16 [n=1024][k=1024]
__device__ __half g_qh[Bn * Hn * Tn * Dn];
__device__ __half g_kh[Bn * Hn * Tn * Dn];
__device__ __half g_vh[Bn * Hn * Tn * Dn];
__device__ __half g_atth[Bn * Tn * Hn * Dn];           // [b][t][h*64+d] fp16

// ---------------------------------------------------------------------------
// mma / ldmatrix / cp.async helpers
// ---------------------------------------------------------------------------
__device__ __forceinline__ void mma_f16(float c[4],
                                        uint32_t a0, uint32_t a1, uint32_t a2, uint32_t a3,
                                        uint32_t b0, uint32_t b1)
{
    asm volatile(
        "mma.sync.aligned.m16n8k16.row.col.f32.f16.f16.f32 "
        "{%0,%1,%2,%3}, {%4,%5,%6,%7}, {%8,%9}, {%0,%1,%2,%3};"
        : "+f"(c[0]), "+f"(c[1]), "+f"(c[2]), "+f"(c[3])
        : "r"(a0), "r"(a1), "r"(a2), "r"(a3), "r"(b0), "r"(b1));
}

__device__ __forceinline__ uint32_t smaddr(const void* p) {
    return (uint32_t)__cvta_generic_to_shared(p);
}

__device__ __forceinline__ void ldsm_x4(uint32_t& r0, uint32_t& r1,
                                        uint32_t& r2, uint32_t& r3, uint32_t addr)
{
    asm volatile("ldmatrix.sync.aligned.m8n8.x4.shared.b16 {%0,%1,%2,%3}, [%4];"
                 : "=r"(r0), "=r"(r1), "=r"(r2), "=r"(r3) : "r"(addr));
}

__device__ __forceinline__ void ldsm_x4_trans(uint32_t& r0, uint32_t& r1,
                                              uint32_t& r2, uint32_t& r3, uint32_t addr)
{
    asm volatile("ldmatrix.sync.aligned.m8n8.x4.trans.shared.b16 {%0,%1,%2,%3}, [%4];"
                 : "=r"(r0), "=r"(r1), "=r"(r2), "=r"(r3) : "r"(addr));
}

__device__ __forceinline__ uint32_t packh2(float lo, float hi) {
    __half2 h = __floats2half2_rn(lo, hi);
    return *(uint32_t*)&h;
}

__device__ __forceinline__ void cp16(uint32_t dst, const void* src) {
    asm volatile("cp.async.cg.shared.global [%0], [%1], 16;" :: "r"(dst), "l"(src));
}
__device__ __forceinline__ void cp_commit() {
    asm volatile("cp.async.commit_group;");
}
__device__ __forceinline__ void cp_wait0() {
    asm volatile("cp.async.wait_group 0;");
}

// ---------------------------------------------------------------------------
// Pre-pass: convert x -> fp16
// ---------------------------------------------------------------------------
__global__ __launch_bounds__(256) void conv_x_kernel(const float* __restrict__ src)
{
    int i = (blockIdx.x * 256 + threadIdx.x) * 4;
    float4 v = *(const float4*)&src[i];
    __half2 h0 = __floats2half2_rn(v.x, v.y);
    __half2 h1 = __floats2half2_rn(v.z, v.w);
    uint2 pk = make_uint2(*(uint32_t*)&h0, *(uint32_t*)&h1);
    *(uint2*)&g_hx[i] = pk;
}

// ---------------------------------------------------------------------------
// Pre-pass: transpose + convert Wq/Wk/Wv -> g_hw [48][64][1024]
// ---------------------------------------------------------------------------
__global__ __launch_bounds__(256) void transcvt_w3(
    const float* __restrict__ Wq, const float* __restrict__ Wk,
    const float* __restrict__ Wv)
{
    __shared__ float tile[32][33];
    const int tid = threadIdx.x;
    const int m = blockIdx.z;
    const float* src = (m < 16 ? Wq : (m < 32 ? Wk : Wv)) + (size_t)(m & 15) * Cn * Dn;
    __half* dst = g_hw + (size_t)m * Dn * Cn;
    const int r0 = blockIdx.y * 32;
    const int c0 = blockIdx.x * 32;

    {
        int rr = tid >> 3;
        int cc = (tid & 7) * 4;
        float4 v = *(const float4*)&src[(size_t)(r0 + rr) * Dn + c0 + cc];
        tile[rr][cc + 0] = v.x;
        tile[rr][cc + 1] = v.y;
        tile[rr][cc + 2] = v.z;
        tile[rr][cc + 3] = v.w;
    }
    __syncthreads();
    {
        int cw = tid >> 3;
        int rw = (tid & 7) * 4;
        __half2 h0 = __floats2half2_rn(tile[rw + 0][cw], tile[rw + 1][cw]);
        __half2 h1 = __floats2half2_rn(tile[rw + 2][cw], tile[rw + 3][cw]);
        uint2 pk = make_uint2(*(uint32_t*)&h0, *(uint32_t*)&h1);
        *(uint2*)&dst[(size_t)(c0 + cw) * Cn + r0 + rw] = pk;
    }
}

// ---------------------------------------------------------------------------
// Pre-pass: transpose + convert Wp -> g_hwpt [n][k]
// ---------------------------------------------------------------------------
__global__ __launch_bounds__(256) void transcvt_kernel(
    const float* __restrict__ src, __half* __restrict__ dst, int R, int C)
{
    __shared__ float tile[32][33];
    const int tid = threadIdx.x;
    const int r0 = blockIdx.y * 32;
    const int c0 = blockIdx.x * 32;

    {
        int rr = tid >> 3;
        int cc = (tid & 7) * 4;
        float4 v = *(const float4*)&src[(size_t)(r0 + rr) * C + c0 + cc];
        tile[rr][cc + 0] = v.x;
        tile[rr][cc + 1] = v.y;
        tile[rr][cc + 2] = v.z;
        tile[rr][cc + 3] = v.w;
    }
    __syncthreads();
    {
        int cw = tid >> 3;
        int rw = (tid & 7) * 4;
        __half2 h0 = __floats2half2_rn(tile[rw + 0][cw], tile[rw + 1][cw]);
        __half2 h1 = __floats2half2_rn(tile[rw + 2][cw], tile[rw + 3][cw]);
        uint2 pk = make_uint2(*(uint32_t*)&h0, *(uint32_t*)&h1);
        *(uint2*)&dst[(size_t)(c0 + cw) * R + r0 + rw] = pk;
    }
}

// ---------------------------------------------------------------------------
// Kernel 1: fused QKV projection, fp16 mma + ldmatrix + cp.async 2-stage.
// Block tile 128x128 (2 heads), Kc=64. Dynamic smem: 2 stages x (As+Bs).
// ---------------------------------------------------------------------------
#define GEMM_STAGE_HALFS (256 * 72)     // As 128*72 + Bs 128*72
#define GEMM_SMEM_BYTES (2 * GEMM_STAGE_HALFS * 2)

__global__ __launch_bounds__(256) void qkv_fp16()
{
    extern __shared__ __align__(16) __half sm[];

    const int tid = threadIdx.x;
    const int lane = tid & 31;
    const int warp = tid >> 5;
    const int g = lane >> 2;
    const int tg = lane & 3;
    const int wmBase = (warp & 3) * 32;
    const int wnBase = (warp >> 2) * 64;

    const int rowBase = blockIdx.x * 128;
    const int py = blockIdx.y;
    const int proj = py >> 3;
    const int hp = py & 7;

    const __half* A = g_hx + (size_t)rowBase * Cn;
    const __half* B = g_hw + (size_t)(proj * Hn + hp * 2) * Dn * Cn;

    __half* outbase = (proj == 0 ? g_qh : (proj == 1 ? g_kh : g_vh));
    const int b  = rowBase >> 10;
    const int t0 = rowBase & (Tn - 1);

    const int ar = tid >> 1;
    const int ah = (tid & 1) * 32;
    const int r16 = lane & 15;
    const int ch = (lane >> 4) * 8;

    // cp.async copy of one stage at K offset k0
    auto stage_load = [&](int s, int k0) {
        __half* As = sm + s * GEMM_STAGE_HALFS;
        __half* Bs = As + 128 * 72;
#pragma unroll
        for (int i = 0; i < 4; i++) {
            cp16(smaddr(&As[ar * 72 + ah + i * 8]), &A[(size_t)ar * Cn + k0 + ah + i * 8]);
            cp16(smaddr(&Bs[ar * 72 + ah + i * 8]), &B[(size_t)ar * Cn + k0 + ah + i * 8]);
        }
        cp_commit();
    };

    float acc[2][8][4];
#pragma unroll
    for (int mt = 0; mt < 2; mt++)
#pragma unroll
        for (int j = 0; j < 8; j++)
#pragma unroll
            for (int e = 0; e < 4; e++) acc[mt][j][e] = 0.f;

    stage_load(0, 0);
    int cur = 0;

    for (int k0 = 0; k0 < Cn; k0 += 64) {
        cp_wait0();
        __syncthreads();
        if (k0 + 64 < Cn) stage_load(cur ^ 1, k0 + 64);

        const __half* As = sm + cur * GEMM_STAGE_HALFS;
        const __half* Bs = As + 128 * 72;

#pragma unroll
        for (int kk = 0; kk < 4; kk++) {
            const int kb = kk * 16;
            uint32_t af[2][4], bf0[8], bf1[8];
#pragma unroll
            for (int mt = 0; mt < 2; mt++)
                ldsm_x4(af[mt][0], af[mt][1], af[mt][2], af[mt][3],
                        smaddr(&As[(wmBase + mt * 16 + r16) * 72 + kb + ch]));
            ldsm_x4(bf0[0], bf0[1], bf0[2], bf0[3],
                    smaddr(&Bs[(wnBase + lane) * 72 + kb]));
            ldsm_x4(bf0[4], bf0[5], bf0[6], bf0[7],
                    smaddr(&Bs[(wnBase + 32 + lane) * 72 + kb]));
            ldsm_x4(bf1[0], bf1[1], bf1[2], bf1[3],
                    smaddr(&Bs[(wnBase + lane) * 72 + kb + 8]));
            ldsm_x4(bf1[4], bf1[5], bf1[6], bf1[7],
                    smaddr(&Bs[(wnBase + 32 + lane) * 72 + kb + 8]));
#pragma unroll
            for (int mt = 0; mt < 2; mt++)
#pragma unroll
                for (int j = 0; j < 8; j++)
                    mma_f16(acc[mt][j], af[mt][0], af[mt][1], af[mt][2], af[mt][3],
                            bf0[j], bf1[j]);
        }
        cur ^= 1;
    }

#pragma unroll
    for (int mt = 0; mt < 2; mt++) {
        int row0 = wmBase + mt * 16 + g;
#pragma unroll
        for (int j = 0; j < 8; j++) {
            int col = wnBase + j * 8 + tg * 2;
            int h = hp * 2 + (col >> 6);
            int d = col & 63;
            __half* ob = outbase + ((size_t)(b * Hn + h) * Tn + t0) * Dn + d;
            *(__half2*)&ob[(size_t)row0 * Dn] =
                __floats2half2_rn(acc[mt][j][0], acc[mt][j][1]);
            *(__half2*)&ob[(size_t)(row0 + 8) * Dn] =
                __floats2half2_rn(acc[mt][j][2], acc[mt][j][3]);
        }
    }
}

// ---------------------------------------------------------------------------
// Kernel 2: causal flash attention, fp16 mma + ldmatrix + cp.async 2-stage K/V.
// One __syncthreads per key tile.
// ---------------------------------------------------------------------------
#define ATTN_KV_STAGE_HALFS (128 * 72)   // Ks 64*72 + Vs 64*72
#define ATTN_SMEM_HALFS (128 * 72 + 2 * ATTN_KV_STAGE_HALFS)

__global__ __launch_bounds__(256) void attn_fp16()
{
    extern __shared__ __align__(16) __half smh[];
    __half* Qs = smh;                        // [128][72] staging only
    __half* KV = smh + 128 * 72;             // 2 stages of (Ks,Vs)

    const int tid = threadIdx.x;
    const int lane = tid & 31;
    const int warp = tid >> 5;
    const int g = lane >> 2;
    const int tg = lane & 3;
    const int wm = warp * 16;
    const int qt = (int)gridDim.x - 1 - (int)blockIdx.x;
    const int bh = blockIdx.y;

    const int r16 = lane & 15;
    const int ch = (lane >> 4) * 8;

    // ---- stage Q (warp-private stripe), hoist fragments to registers ----
    uint32_t qf[4][4];
    {
        const __half* qb = g_qh + ((size_t)bh * Tn + (size_t)qt * 128) * Dn;
        int r = tid >> 1;
        int hs = (tid & 1) * 32;
#pragma unroll
        for (int i = 0; i < 4; i++)
            *(uint4*)&Qs[r * 72 + hs + i * 8] =
                *(const uint4*)&qb[(size_t)r * Dn + hs + i * 8];
        __syncwarp();
#pragma unroll
        for (int kk = 0; kk < 4; kk++)
            ldsm_x4(qf[kk][0], qf[kk][1], qf[kk][2], qf[kk][3],
                    smaddr(&Qs[(wm + r16) * 72 + kk * 16 + ch]));
    }

    float m0 = -CUDART_INF_F, m1 = -CUDART_INF_F;
    float l0 = 0.f, l1 = 0.f;
    float oacc[8][4];
#pragma unroll
    for (int j = 0; j < 8; j++)
#pragma unroll
        for (int e = 0; e < 4; e++) oacc[j][e] = 0.f;

    const int row0 = qt * 128 + wm + g;
    const int row1 = row0 + 8;
    const int rowWarpMax = qt * 128 + wm + 15;

    const __half* kbase = g_kh + (size_t)bh * Tn * Dn;
    const __half* vbase = g_vh + (size_t)bh * Tn * Dn;
    const int sr = tid >> 2;
    const int sh = (tid & 3) * 16;

    auto kv_load = [&](int s, int st) {
        __half* Ks = KV + s * ATTN_KV_STAGE_HALFS;
        __half* Vs = Ks + 64 * 72;
        const __half* kn = kbase + (size_t)st * 64 * Dn;
        const __half* vn = vbase + (size_t)st * 64 * Dn;
#pragma unroll
        for (int i = 0; i < 2; i++) {
            cp16(smaddr(&Ks[sr * 72 + sh + i * 8]), &kn[(size_t)sr * Dn + sh + i * 8]);
            cp16(smaddr(&Vs[sr * 72 + sh + i * 8]), &vn[(size_t)sr * Dn + sh + i * 8]);
        }
        cp_commit();
    };

    kv_load(0, 0);
    int cur = 0;

    const int nst = 2 * qt + 2;
    for (int st = 0; st < nst; st++) {
        cp_wait0();
        __syncthreads();
        if (st + 1 < nst) kv_load(cur ^ 1, st + 1);

        if (st * 64 <= rowWarpMax) {
            const __half* Ks = KV + cur * ATTN_KV_STAGE_HALFS;
            const __half* Vs = Ks + 64 * 72;

            // ---- S = Q K^T (16 x 64 per warp) ----
            float c[8][4];
#pragma unroll
            for (int j = 0; j < 8; j++)
#pragma unroll
                for (int e = 0; e < 4; e++) c[j][e] = 0.f;

#pragma unroll
            for (int kk = 0; kk < 4; kk++) {
                const int kb = kk * 16;
                uint32_t b0lo[4], b0hi[4], b1lo[4], b1hi[4];
                ldsm_x4(b0lo[0], b0lo[1], b0lo[2], b0lo[3],
                        smaddr(&Ks[lane * 72 + kb]));
                ldsm_x4(b0hi[0], b0hi[1], b0hi[2], b0hi[3],
                        smaddr(&Ks[(32 + lane) * 72 + kb]));
                ldsm_x4(b1lo[0], b1lo[1], b1lo[2], b1lo[3],
                        smaddr(&Ks[lane * 72 + kb + 8]));
                ldsm_x4(b1hi[0], b1hi[1], b1hi[2], b1hi[3],
                        smaddr(&Ks[(32 + lane) * 72 + kb + 8]));
#pragma unroll
                for (int j = 0; j < 4; j++) {
                    mma_f16(c[j], qf[kk][0], qf[kk][1], qf[kk][2], qf[kk][3],
                            b0lo[j], b1lo[j]);
                    mma_f16(c[j + 4], qf[kk][0], qf[kk][1], qf[kk][2], qf[kk][3],
                            b0hi[j], b1hi[j]);
                }
            }

            // ---- scale + causal mask ----
            const float scale = 0.125f;
            const bool maskt = (st * 64 + 63 > qt * 128);
#pragma unroll
            for (int j = 0; j < 8; j++) {
                int col = st * 64 + j * 8 + tg * 2;
                if (maskt) {
                    c[j][0] = (col     > row0) ? -CUDART_INF_F : c[j][0] * scale;
                    c[j][1] = (col + 1 > row0) ? -CUDART_INF_F : c[j][1] * scale;
                    c[j][2] = (col     > row1) ? -CUDART_INF_F : c[j][2] * scale;
                    c[j][3] = (col + 1 > row1) ? -CUDART_INF_F : c[j][3] * scale;
                } else {
                    c[j][0] *= scale; c[j][1] *= scale;
                    c[j][2] *= scale; c[j][3] *= scale;
                }
            }

            // ---- online softmax (P stays in registers) ----
            float t0 = -CUDART_INF_F, t1 = -CUDART_INF_F;
#pragma unroll
            for (int j = 0; j < 8; j++) {
                t0 = fmaxf(t0, fmaxf(c[j][0], c[j][1]));
                t1 = fmaxf(t1, fmaxf(c[j][2], c[j][3]));
            }
            t0 = fmaxf(t0, __shfl_xor_sync(0xffffffffu, t0, 1));
            t0 = fmaxf(t0, __shfl_xor_sync(0xffffffffu, t0, 2));
            t1 = fmaxf(t1, __shfl_xor_sync(0xffffffffu, t1, 1));
            t1 = fmaxf(t1, __shfl_xor_sync(0xffffffffu, t1, 2));

            float nm0 = fmaxf(m0, t0), nm1 = fmaxf(m1, t1);
            float al0 = __expf(m0 - nm0), al1 = __expf(m1 - nm1);
            float s0 = 0.f, s1 = 0.f;
#pragma unroll
            for (int j = 0; j < 8; j++) {
                c[j][0] = __expf(c[j][0] - nm0);
                c[j][1] = __expf(c[j][1] - nm0);
                c[j][2] = __expf(c[j][2] - nm1);
                c[j][3] = __expf(c[j][3] - nm1);
                s0 += c[j][0] + c[j][1];
                s1 += c[j][2] + c[j][3];
            }
            s0 += __shfl_xor_sync(0xffffffffu, s0, 1);
            s0 += __shfl_xor_sync(0xffffffffu, s0, 2);
            s1 += __shfl_xor_sync(0xffffffffu, s1, 1);
            s1 += __shfl_xor_sync(0xffffffffu, s1, 2);

            l0 = l0 * al0 + s0;  m0 = nm0;
            l1 = l1 * al1 + s1;  m1 = nm1;

#pragma unroll
            for (int j = 0; j < 8; j++) {
                oacc[j][0] *= al0; oacc[j][1] *= al0;
                oacc[j][2] *= al1; oacc[j][3] *= al1;
            }

            // ---- O += P V : P from registers, V via trans-ldmatrix ----
#pragma unroll
            for (int kk = 0; kk < 4; kk++) {
                const int kb = kk * 16;
                uint32_t a0 = packh2(c[2 * kk][0], c[2 * kk][1]);
                uint32_t a1 = packh2(c[2 * kk][2], c[2 * kk][3]);
                uint32_t a2 = packh2(c[2 * kk + 1][0], c[2 * kk + 1][1]);
                uint32_t a3 = packh2(c[2 * kk + 1][2], c[2 * kk + 1][3]);

                uint32_t v0lo[4], v0hi[4], v1lo[4], v1hi[4];
                const int srow = lane & 7;
                const int dcol = (lane >> 3) * 8;
                ldsm_x4_trans(v0lo[0], v0lo[1], v0lo[2], v0lo[3],
                              smaddr(&Vs[(kb + srow) * 72 + dcol]));
                ldsm_x4_trans(v0hi[0], v0hi[1], v0hi[2], v0hi[3],
                              smaddr(&Vs[(kb + srow) * 72 + dcol + 32]));
                ldsm_x4_trans(v1lo[0], v1lo[1], v1lo[2], v1lo[3],
                              smaddr(&Vs[(kb + 8 + srow) * 72 + dcol]));
                ldsm_x4_trans(v1hi[0], v1hi[1], v1hi[2], v1hi[3],
                              smaddr(&Vs[(kb + 8 + srow) * 72 + dcol + 32]));
#pragma unroll
                for (int j = 0; j < 4; j++) {
                    mma_f16(oacc[j], a0, a1, a2, a3, v0lo[j], v1lo[j]);
                    mma_f16(oacc[j + 4], a0, a1, a2, a3, v0hi[j], v1hi[j]);
                }
            }
        }
        cur ^= 1;
    }

    // ---- epilogue -> g_atth [b][t][h*64+d] fp16 ----
    const int b = bh >> 4, h = bh & 15;
    __half* ob = g_atth + ((size_t)b * Tn + (size_t)qt * 128) * (Hn * Dn) + h * Dn;
    float inv0 = 1.f / l0, inv1 = 1.f / l1;
#pragma unroll
    for (int j = 0; j < 8; j++) {
        int col = j * 8 + tg * 2;
        *(__half2*)&ob[(size_t)(wm + g) * (Hn * Dn) + col] =
            __floats2half2_rn(oacc[j][0] * inv0, oacc[j][1] * inv0);
        *(__half2*)&ob[(size_t)(wm + g + 8) * (Hn * Dn) + col] =
            __floats2half2_rn(oacc[j][2] * inv1, oacc[j][3] * inv1);
    }
}

// ---------------------------------------------------------------------------
// Kernel 3: output projection, fp16 mma + ldmatrix + cp.async 2-stage.
// Block tile 128x128.
// ---------------------------------------------------------------------------
__global__ __launch_bounds__(256) void proj_fp16(
    const float* __restrict__ bp, float* __restrict__ out)
{
    extern __shared__ __align__(16) __half sm[];

    const int tid = threadIdx.x;
    const int lane = tid & 31;
    const int warp = tid >> 5;
    const int g = lane >> 2;
    const int tg = lane & 3;
    const int wmBase = (warp & 3) * 32;
    const int wnBase = (warp >> 2) * 64;

    const int rowBase = blockIdx.x * 128;
    const int n0 = blockIdx.y * 128;

    const __half* A = g_atth + (size_t)rowBase * Cn;
    const __half* B = g_hwpt + (size_t)n0 * Cn;
    float* O = out + (size_t)rowBase * Cn + n0;

    const int ar = tid >> 1;
    const int ah = (tid & 1) * 32;
    const int r16 = lane & 15;
    const int ch = (lane >> 4) * 8;

    auto stage_load = [&](int s, int k0) {
        __half* As = sm + s * GEMM_STAGE_HALFS;
        __half* Bs = As + 128 * 72;
#pragma unroll
        for (int i = 0; i < 4; i++) {
            cp16(smaddr(&As[ar * 72 + ah + i * 8]), &A[(size_t)ar * Cn + k0 + ah + i * 8]);
            cp16(smaddr(&Bs[ar * 72 + ah + i * 8]), &B[(size_t)ar * Cn + k0 + ah + i * 8]);
        }
        cp_commit();
    };

    float acc[2][8][4];
#pragma unroll
    for (int mt = 0; mt < 2; mt++)
#pragma unroll
        for (int j = 0; j < 8; j++)
#pragma unroll
            for (int e = 0; e < 4; e++) acc[mt][j][e] = 0.f;

    stage_load(0, 0);
    int cur = 0;

    for (int k0 = 0; k0 < Cn; k0 += 64) {
        cp_wait0();
        __syncthreads();
        if (k0 + 64 < Cn) stage_load(cur ^ 1, k0 + 64);

        const __half* As = sm + cur * GEMM_STAGE_HALFS;
        const __half* Bs = As + 128 * 72;

#pragma unroll
        for (int kk = 0; kk < 4; kk++) {
            const int kb = kk * 16;
            uint32_t af[2][4], bf0[8], bf1[8];
#pragma unroll
            for (int mt = 0; mt < 2; mt++)
                ldsm_x4(af[mt][0], af[mt][1], af[mt][2], af[mt][3],
                        smaddr(&As[(wmBase + mt * 16 + r16) * 72 + kb + ch]));
            ldsm_x4(bf0[0], bf0[1], bf0[2], bf0[3],
                    smaddr(&Bs[(wnBase + lane) * 72 + kb]));
            ldsm_x4(bf0[4], bf0[5], bf0[6], bf0[7],
                    smaddr(&Bs[(wnBase + 32 + lane) * 72 + kb]));
            ldsm_x4(bf1[0], bf1[1], bf1[2], bf1[3],
                    smaddr(&Bs[(wnBase + lane) * 72 + kb + 8]));
            ldsm_x4(bf1[4], bf1[5], bf1[6], bf1[7],
                    smaddr(&Bs[(wnBase + 32 + lane) * 72 + kb + 8]));
#pragma unroll
            for (int mt = 0; mt < 2; mt++)
#pragma unroll
                for (int j = 0; j < 8; j++)
                    mma_f16(acc[mt][j], af[mt][0], af[mt][1], af[mt][2], af[mt][3],
                            bf0[j], bf1[j]);
        }
        cur ^= 1;
    }

#pragma unroll
    for (int mt = 0; mt < 2; mt++) {
        int row0 = wmBase + mt * 16 + g;
#pragma unroll
        for (int j = 0; j < 8; j++) {
            int col = wnBase + j * 8 + tg * 2;
            float b0 = bp[n0 + col];
            float b1 = bp[n0 + col + 1];
            *(float2*)&O[(size_t)row0 * Cn + col] =
                make_float2(acc[mt][j][0] + b0, acc[mt][j][1] + b1);
            *(float2*)&O[(size_t)(row0 + 8) * Cn + col] =
                make_float2(acc[mt][j][2] + b0, acc[mt][j][3] + b1);
        }
    }
}

// ---------------------------------------------------------------------------

extern "C" void kernel_launch(void* const* d_in, const int* in_sizes, int n_in,
                              void* d_out, int out_size)
{
    (void)in_sizes; (void)n_in; (void)out_size;
    const float* x  = (const float*)d_in[0];
    const float* Wq = (const float*)d_in[1];
    const float* Wk = (const float*)d_in[2];
    const float* Wv = (const float*)d_in[3];
    const float* Wp = (const float*)d_in[4];
    const float* bp = (const float*)d_in[5];
    float* out = (float*)d_out;

    __half* hwpt = nullptr;
    cudaGetSymbolAddress((void**)&hwpt, g_hwpt);

    const size_t attn_smem = ATTN_SMEM_HALFS * sizeof(__half);   // 55296 B
    cudaFuncSetAttribute(attn_fp16,
                         cudaFuncAttributeMaxDynamicSharedMemorySize,
                         (int)attn_smem);
    cudaFuncSetAttribute(qkv_fp16,
                         cudaFuncAttributeMaxDynamicSharedMemorySize,
                         GEMM_SMEM_BYTES);                        // 73728 B
    cudaFuncSetAttribute(proj_fp16,
                         cudaFuncAttributeMaxDynamicSharedMemorySize,
                         GEMM_SMEM_BYTES);

    conv_x_kernel<<<Bn * Tn * Cn / (256 * 4), 256>>>(x);
    transcvt_w3<<<dim3(2, 32, 48), 256>>>(Wq, Wk, Wv);
    transcvt_kernel<<<dim3(32, 32, 1), 256>>>(Wp, hwpt, Cn, Cn);

    qkv_fp16<<<dim3(32, 24), 256, GEMM_SMEM_BYTES>>>();
    attn_fp16<<<dim3(Tn / 128, Bn * Hn), 256, attn_smem>>>();
    proj_fp16<<<dim3(32, 8), 256, GEMM_SMEM_BYTES>>>(bp, out);
}